// round 1
// baseline (speedup 1.0000x reference)
#include <cuda_runtime.h>
#include <math.h>
#include <limits.h>

// ---------------- problem constants ----------------
#define BB 256
#define NN 300
#define IN_DIM 1280
#define DIM 256
#define HEADS 4
#define DH 64
#define MF 266            // NB_FEAT
#define FFH 1024
#define ROWS_TOT (BB*NN)  // 76800

#define LN_EPS 1e-5f
#define KEPS 1e-4f

// ---------------- scratch ----------------
__device__ float g_h  [ROWS_TOT*DIM];
__device__ float g_y  [ROWS_TOT*DIM];
__device__ float g_q  [ROWS_TOT*DIM];
__device__ float g_k  [ROWS_TOT*DIM];
__device__ float g_v  [ROWS_TOT*DIM];
__device__ float g_o  [ROWS_TOT*DIM];
__device__ float g_ffh[ROWS_TOT*FFH];
__device__ float g_qp [BB*HEADS*NN*MF];
__device__ float g_kp [BB*HEADS*NN*MF];
__device__ float g_ctx[BB*HEADS*MF*DH];
__device__ float g_ksum[BB*HEADS*MF];
__device__ int   g_kmax[BB*HEADS];
__device__ float g_pool[BB*DIM];
__device__ float g_z  [BB*DIM];
__device__ float g_z1 [BB*128];

// ---------------- helpers ----------------
__device__ __forceinline__ int f2o(float f) {
    int i = __float_as_int(f);
    return i >= 0 ? i : (i ^ 0x7FFFFFFF);
}
__device__ __forceinline__ float o2f(int i) {
    return __int_as_float(i >= 0 ? i : (i ^ 0x7FFFFFFF));
}
__device__ __forceinline__ float gelu_tanh(float x) {
    float x3 = x * x * x;
    return 0.5f * x * (1.0f + tanhf(0.7978845608028654f * (x + 0.044715f * x3)));
}

__device__ __forceinline__ float blockReduceSum256(float v) {
    __shared__ float sh[8];
    __syncthreads();
    int lane = threadIdx.x & 31, w = threadIdx.x >> 5;
    #pragma unroll
    for (int o = 16; o; o >>= 1) v += __shfl_xor_sync(0xFFFFFFFFu, v, o);
    if (lane == 0) sh[w] = v;
    __syncthreads();
    if (threadIdx.x == 0) {
        float s = 0.f;
        #pragma unroll
        for (int i = 0; i < 8; i++) s += sh[i];
        sh[0] = s;
    }
    __syncthreads();
    return sh[0];
}

// ---------------- generic tiled SGEMM ----------------
// C[M,N] = act(A[M,K] @ B[K,N] + bias) + res   (act: 0=none, 1=gelu)
// Requires M%128==0, N%64==0, K%16==0.
__global__ void __launch_bounds__(256) sgemm_kernel(
    const float* __restrict__ A, const float* __restrict__ Bm,
    const float* __restrict__ bias, const float* __restrict__ res,
    float* __restrict__ C, int M, int N, int K, int act)
{
    __shared__ float As[16][132];
    __shared__ float Bs[16][64];
    const int tid = threadIdx.x;
    const int tx = tid & 15, ty = tid >> 4;
    const int row0 = blockIdx.y * 128, col0 = blockIdx.x * 64;

    float acc[8][4];
    #pragma unroll
    for (int i = 0; i < 8; i++)
        #pragma unroll
        for (int j = 0; j < 4; j++) acc[i][j] = 0.f;

    const int aRow = tid >> 1;
    const int aCol = (tid & 1) * 8;
    const int bCol = tid & 63;
    const int bRow = tid >> 6;      // 0..3

    const float* Aptr = A + (size_t)(row0 + aRow) * K + aCol;
    const float* Bptr = Bm + (size_t)bRow * N + col0 + bCol;

    for (int k0 = 0; k0 < K; k0 += 16) {
        float4 a0 = *(const float4*)(Aptr);
        float4 a1 = *(const float4*)(Aptr + 4);
        As[aCol + 0][aRow] = a0.x; As[aCol + 1][aRow] = a0.y;
        As[aCol + 2][aRow] = a0.z; As[aCol + 3][aRow] = a0.w;
        As[aCol + 4][aRow] = a1.x; As[aCol + 5][aRow] = a1.y;
        As[aCol + 6][aRow] = a1.z; As[aCol + 7][aRow] = a1.w;
        #pragma unroll
        for (int r = 0; r < 4; r++)
            Bs[bRow + r * 4][bCol] = Bptr[(size_t)(r * 4) * N];
        __syncthreads();

        #pragma unroll
        for (int kk = 0; kk < 16; kk++) {
            float4 bA = *(const float4*)&Bs[kk][tx * 4];
            float4 aA = *(const float4*)&As[kk][ty * 8];
            float4 aB = *(const float4*)&As[kk][ty * 8 + 4];
            float ra[8] = {aA.x, aA.y, aA.z, aA.w, aB.x, aB.y, aB.z, aB.w};
            float rb[4] = {bA.x, bA.y, bA.z, bA.w};
            #pragma unroll
            for (int i = 0; i < 8; i++)
                #pragma unroll
                for (int j = 0; j < 4; j++)
                    acc[i][j] = fmaf(ra[i], rb[j], acc[i][j]);
        }
        __syncthreads();
        Aptr += 16;
        Bptr += (size_t)16 * N;
    }

    #pragma unroll
    for (int i = 0; i < 8; i++) {
        int r = row0 + ty * 8 + i;
        #pragma unroll
        for (int j = 0; j < 4; j++) {
            int c = col0 + tx * 4 + j;
            float v = acc[i][j];
            if (bias) v += bias[c];
            if (act == 1) v = gelu_tanh(v);
            if (res) v += res[(size_t)r * N + c];
            C[(size_t)r * N + c] = v;
        }
    }
}

// ---------------- layernorm (dim 256, 1 row per block) ----------------
__global__ void ln_kernel(const float* __restrict__ x, const float* __restrict__ g,
                          const float* __restrict__ b, float* __restrict__ y)
{
    int row = blockIdx.x;
    int t = threadIdx.x;
    float v = x[(size_t)row * DIM + t];
    float mu = blockReduceSum256(v) * (1.0f / DIM);
    float d = v - mu;
    float var = blockReduceSum256(d * d) * (1.0f / DIM);
    y[(size_t)row * DIM + t] = d * rsqrtf(var + LN_EPS) * g[t] + b[t];
}

// ---------------- FAVOR+ feature kernels ----------------
// q/k buffers: [B, N, DIM], head h = cols [h*64, h*64+64)
// qp/kp: [B*H, N, MF]
__global__ void feat_q_kernel(const float* __restrict__ q, const float* __restrict__ proj,
                              float* __restrict__ qp)
{
    __shared__ float qs[16][64];
    __shared__ float dd[16][MF];
    __shared__ int smax[16];
    __shared__ float diag[16];
    const float NORM = 0.35355339059327373f;   // 64^-0.25
    const float RATIO = 0.061314066f;          // 266^-0.5

    int bh = blockIdx.x, b = bh >> 2, head = bh & 3;
    int n0 = blockIdx.y * 16;
    int rows = min(16, NN - n0);
    int tid = threadIdx.x;

    for (int idx = tid; idx < 16 * 64; idx += 256) {
        int r = idx >> 6, d = idx & 63;
        float val = 0.f;
        if (r < rows) val = q[((size_t)(b * NN + n0 + r)) * DIM + head * 64 + d] * NORM;
        qs[r][d] = val;
    }
    __syncthreads();
    if (tid < 16) {
        float s = 0.f;
        #pragma unroll
        for (int d = 0; d < 64; d++) s += qs[tid][d] * qs[tid][d];
        diag[tid] = 0.5f * s;
        smax[tid] = INT_MIN;
    }
    __syncthreads();

    for (int m = tid; m < MF; m += 256) {
        const float* pr = proj + m * DH;
        float acc[16];
        #pragma unroll
        for (int r = 0; r < 16; r++) acc[r] = 0.f;
        #pragma unroll 4
        for (int d = 0; d < 64; d++) {
            float p = pr[d];
            #pragma unroll
            for (int r = 0; r < 16; r++) acc[r] = fmaf(p, qs[r][d], acc[r]);
        }
        #pragma unroll
        for (int r = 0; r < 16; r++) dd[r][m] = acc[r];
        for (int r = 0; r < rows; r++) atomicMax(&smax[r], f2o(acc[r]));
    }
    __syncthreads();

    for (int m = tid; m < MF; m += 256) {
        for (int r = 0; r < rows; r++) {
            float stab = o2f(smax[r]);
            float val = RATIO * (expf(dd[r][m] - diag[r] - stab) + KEPS);
            qp[((size_t)bh * NN + n0 + r) * MF + m] = val;
        }
    }
}

// pass1: write dd - diag to kp; track global max(dd) per (b,h)
__global__ void feat_k_kernel(const float* __restrict__ k, const float* __restrict__ proj,
                              float* __restrict__ kp, int* __restrict__ kmax)
{
    __shared__ float qs[16][64];
    __shared__ float diag[16];
    __shared__ int bmax;
    const float NORM = 0.35355339059327373f;

    int bh = blockIdx.x, b = bh >> 2, head = bh & 3;
    int n0 = blockIdx.y * 16;
    int rows = min(16, NN - n0);
    int tid = threadIdx.x;

    for (int idx = tid; idx < 16 * 64; idx += 256) {
        int r = idx >> 6, d = idx & 63;
        float val = 0.f;
        if (r < rows) val = k[((size_t)(b * NN + n0 + r)) * DIM + head * 64 + d] * NORM;
        qs[r][d] = val;
    }
    if (tid == 0) bmax = INT_MIN;
    __syncthreads();
    if (tid < 16) {
        float s = 0.f;
        #pragma unroll
        for (int d = 0; d < 64; d++) s += qs[tid][d] * qs[tid][d];
        diag[tid] = 0.5f * s;
    }
    __syncthreads();

    float lmax = -INFINITY;
    for (int m = tid; m < MF; m += 256) {
        const float* pr = proj + m * DH;
        float acc[16];
        #pragma unroll
        for (int r = 0; r < 16; r++) acc[r] = 0.f;
        #pragma unroll 4
        for (int d = 0; d < 64; d++) {
            float p = pr[d];
            #pragma unroll
            for (int r = 0; r < 16; r++) acc[r] = fmaf(p, qs[r][d], acc[r]);
        }
        for (int r = 0; r < rows; r++) {
            lmax = fmaxf(lmax, acc[r]);
            kp[((size_t)bh * NN + n0 + r) * MF + m] = acc[r] - diag[r];
        }
    }
    atomicMax(&bmax, f2o(lmax));
    __syncthreads();
    if (tid == 0) atomicMax(&kmax[bh], bmax);
}

__global__ void kmax_init_kernel(int* __restrict__ kmax) {
    int i = blockIdx.x * blockDim.x + threadIdx.x;
    if (i < BB * HEADS) kmax[i] = INT_MIN;
}

// pass2: kp = ratio*(exp(val - stab) + eps)
__global__ void kexp_kernel(float* __restrict__ kp, const int* __restrict__ kmax)
{
    const float RATIO = 0.061314066f;
    int bh = blockIdx.x;
    int t = blockIdx.y * blockDim.x + threadIdx.x;
    if (t >= NN * MF) return;
    float stab = o2f(kmax[bh]);
    size_t i = (size_t)bh * NN * MF + t;
    kp[i] = RATIO * (expf(kp[i] - stab) + KEPS);
}

__global__ void ksum_kernel(const float* __restrict__ kp, float* __restrict__ ksum)
{
    int bh = blockIdx.x;
    for (int m = threadIdx.x; m < MF; m += blockDim.x) {
        float s = 0.f;
        const float* p = kp + (size_t)bh * NN * MF + m;
        for (int n = 0; n < NN; n++) s += p[(size_t)n * MF];
        ksum[bh * MF + m] = s;
    }
}

// context[bh, m, d] = sum_n kp[bh,n,m] * v[b,n,head*64+d]
__global__ void ctx_kernel(const float* __restrict__ kp, const float* __restrict__ v,
                           float* __restrict__ ctx)
{
    extern __shared__ float vs[];  // NN*64
    int bh = blockIdx.x, b = bh >> 2, head = bh & 3;
    int tid = threadIdx.x;
    for (int idx = tid; idx < NN * 64; idx += 256) {
        int n = idx >> 6, d = idx & 63;
        vs[idx] = v[((size_t)(b * NN + n)) * DIM + head * 64 + d];
    }
    __syncthreads();
    int d = tid & 63, mg = tid >> 6;
    for (int m = mg; m < MF; m += 4) {
        const float* kpr = kp + (size_t)bh * NN * MF + m;
        float acc = 0.f;
        #pragma unroll 4
        for (int n = 0; n < NN; n++)
            acc = fmaf(kpr[(size_t)n * MF], vs[n * 64 + d], acc);
        ctx[((size_t)bh * MF + m) * 64 + d] = acc;
    }
}

// o[b,n,head*64+d] = (qp[n,:] . ctx[:,d]) / (qp[n,:] . ksum)
__global__ void attnout_kernel(const float* __restrict__ qp, const float* __restrict__ ctx,
                               const float* __restrict__ ksum, float* __restrict__ o)
{
    extern __shared__ float cs[];           // MF*64 + MF
    float* ks = cs + MF * 64;
    int bh = blockIdx.x, b = bh >> 2, head = bh & 3;
    int tid = threadIdx.x;
    for (int idx = tid; idx < MF * 64; idx += 256) cs[idx] = ctx[(size_t)bh * MF * 64 + idx];
    for (int m = tid; m < MF; m += 256) ks[m] = ksum[bh * MF + m];
    __syncthreads();
    int d = tid & 63, ng = tid >> 6;
    for (int n = ng; n < NN; n += 4) {
        const float* qpr = qp + ((size_t)bh * NN + n) * MF;
        float acc = 0.f, den = 0.f;
        #pragma unroll 2
        for (int m = 0; m < MF; m++) {
            float qv = qpr[m];
            acc = fmaf(qv, cs[m * 64 + d], acc);
            den = fmaf(qv, ks[m], den);
        }
        o[((size_t)(b * NN + n)) * DIM + head * 64 + d] = acc / den;
    }
}

// ---------------- pooling & head ----------------
__global__ void pool_kernel(const float* __restrict__ h, float* __restrict__ pooled)
{
    int b = blockIdx.x, c = threadIdx.x;
    float s = 0.f;
    for (int n = 0; n < NN; n++) s += h[((size_t)(b * NN + n)) * DIM + c];
    pooled[b * DIM + c] = s * (1.0f / NN);
}

__global__ void head1_kernel(const float* __restrict__ z, const float* __restrict__ w,
                             const float* __restrict__ bias, float* __restrict__ z1)
{
    __shared__ float zs[DIM];
    int b = blockIdx.x, j = threadIdx.x;   // 128 threads
    for (int c = j; c < DIM; c += 128) zs[c] = z[b * DIM + c];
    __syncthreads();
    float s = bias[j];
    #pragma unroll 4
    for (int c = 0; c < DIM; c++) s = fmaf(zs[c], w[c * 128 + j], s);
    z1[b * 128 + j] = fmaxf(s, 0.f);
}

__global__ void head2_kernel(const float* __restrict__ z1, const float* __restrict__ w,
                             const float* __restrict__ bias, float* __restrict__ out)
{
    __shared__ float sh[4];
    int b = blockIdx.x, j = threadIdx.x;   // 128 threads
    float s = z1[b * 128 + j] * w[j];
    #pragma unroll
    for (int o = 16; o; o >>= 1) s += __shfl_xor_sync(0xFFFFFFFFu, s, o);
    if ((j & 31) == 0) sh[j >> 5] = s;
    __syncthreads();
    if (j == 0) {
        float t = sh[0] + sh[1] + sh[2] + sh[3] + bias[0];
        out[b] = 1.0f / (1.0f + expf(-t));
    }
}

// ---------------- host ----------------
static float* symaddr(const void* sym) {
    void* p = nullptr;
    cudaGetSymbolAddress(&p, sym);
    return (float*)p;
}

extern "C" void kernel_launch(void* const* d_in, const int* in_sizes, int n_in,
                              void* d_out, int out_size)
{
    const float* x     = (const float*)d_in[0];
    const float* w_in  = (const float*)d_in[1];
    const float* b_in  = (const float*)d_in[2];
    const float* proj  = (const float*)d_in[3];
    const float* ln1_g = (const float*)d_in[4];
    const float* ln1_b = (const float*)d_in[5];
    const float* wq    = (const float*)d_in[6];
    const float* wk    = (const float*)d_in[7];
    const float* wv    = (const float*)d_in[8];
    const float* wo    = (const float*)d_in[9];
    const float* bo    = (const float*)d_in[10];
    const float* ln2_g = (const float*)d_in[11];
    const float* ln2_b = (const float*)d_in[12];
    const float* w1    = (const float*)d_in[13];
    const float* b1    = (const float*)d_in[14];
    const float* w2    = (const float*)d_in[15];
    const float* b2    = (const float*)d_in[16];
    const float* hln_g = (const float*)d_in[17];
    const float* hln_b = (const float*)d_in[18];
    const float* wh1   = (const float*)d_in[19];
    const float* bh1   = (const float*)d_in[20];
    const float* wh2   = (const float*)d_in[21];
    const float* bh2   = (const float*)d_in[22];
    float* out = (float*)d_out;

    float* h   = symaddr(g_h);
    float* y   = symaddr(g_y);
    float* q   = symaddr(g_q);
    float* k   = symaddr(g_k);
    float* v   = symaddr(g_v);
    float* o   = symaddr(g_o);
    float* ffh = symaddr(g_ffh);
    float* qp  = symaddr(g_qp);
    float* kp  = symaddr(g_kp);
    float* ctx = symaddr(g_ctx);
    float* ksm = symaddr(g_ksum);
    int*   kmx = (int*)symaddr(g_kmax);
    float* pool = symaddr(g_pool);
    float* z   = symaddr(g_z);
    float* z1  = symaddr(g_z1);

    const int ctx_smem = NN * 64 * 4;                 // 76800 B
    const int out_smem = (MF * 64 + MF) * 4;          // 69160 B
    cudaFuncSetAttribute(ctx_kernel,     cudaFuncAttributeMaxDynamicSharedMemorySize, ctx_smem);
    cudaFuncSetAttribute(attnout_kernel, cudaFuncAttributeMaxDynamicSharedMemorySize, out_smem);

    dim3 blk(256);
    dim3 gN256(DIM / 64, ROWS_TOT / 128);     // N=256
    dim3 gN1024(FFH / 64, ROWS_TOT / 128);    // N=1024
    dim3 featGrid(BB * HEADS, (NN + 15) / 16);

    // h = x @ w_in + b_in
    sgemm_kernel<<<gN256, blk>>>(x, w_in, b_in, nullptr, h, ROWS_TOT, DIM, IN_DIM, 0);

    for (int l = 0; l < 2; l++) {
        const float* projl = proj + (size_t)l * MF * DH;
        // --- attention ---
        ln_kernel<<<ROWS_TOT, 256>>>(h, ln1_g + l * DIM, ln1_b + l * DIM, y);
        sgemm_kernel<<<gN256, blk>>>(y, wq + (size_t)l * DIM * DIM, nullptr, nullptr, q, ROWS_TOT, DIM, DIM, 0);
        sgemm_kernel<<<gN256, blk>>>(y, wk + (size_t)l * DIM * DIM, nullptr, nullptr, k, ROWS_TOT, DIM, DIM, 0);
        sgemm_kernel<<<gN256, blk>>>(y, wv + (size_t)l * DIM * DIM, nullptr, nullptr, v, ROWS_TOT, DIM, DIM, 0);

        kmax_init_kernel<<<1, 1024>>>(kmx);
        feat_q_kernel<<<featGrid, blk>>>(q, projl, qp);
        feat_k_kernel<<<featGrid, blk>>>(k, projl, kp, kmx);
        kexp_kernel<<<dim3(BB * HEADS, (NN * MF + 255) / 256), blk>>>(kp, kmx);
        ksum_kernel<<<BB * HEADS, blk>>>(kp, ksm);
        ctx_kernel<<<BB * HEADS, blk, ctx_smem>>>(kp, v, ctx);
        attnout_kernel<<<BB * HEADS, blk, out_smem>>>(qp, ctx, ksm, o);

        sgemm_kernel<<<gN256, blk>>>(o, wo + (size_t)l * DIM * DIM, bo + l * DIM, h, h, ROWS_TOT, DIM, DIM, 0);

        // --- FFN ---
        ln_kernel<<<ROWS_TOT, 256>>>(h, ln2_g + l * DIM, ln2_b + l * DIM, y);
        sgemm_kernel<<<gN1024, blk>>>(y, w1 + (size_t)l * DIM * FFH, b1 + l * FFH, nullptr, ffh, ROWS_TOT, FFH, DIM, 1);
        sgemm_kernel<<<gN256, blk>>>(ffh, w2 + (size_t)l * FFH * DIM, b2 + l * DIM, h, h, ROWS_TOT, DIM, FFH, 0);
    }

    pool_kernel<<<BB, 256>>>(h, pool);
    ln_kernel<<<BB, 256>>>(pool, hln_g, hln_b, z);
    head1_kernel<<<BB, 128>>>(z, wh1, bh1, z1);
    head2_kernel<<<BB, 128>>>(z1, wh2, bh2, out);
}

// round 2
// speedup vs baseline: 1.0125x; 1.0125x over previous
#include <cuda_runtime.h>
#include <math.h>
#include <limits.h>

// ---------------- problem constants ----------------
#define BB 256
#define NN 300
#define IN_DIM 1280
#define DIM 256
#define HEADS 4
#define DH 64
#define MF 266            // NB_FEAT
#define FFH 1024
#define ROWS_TOT (BB*NN)  // 76800

#define LN_EPS 1e-5f
#define KEPS 1e-4f

// ---------------- scratch ----------------
__device__ float g_h  [ROWS_TOT*DIM];
__device__ float g_y  [ROWS_TOT*DIM];
__device__ float g_q  [ROWS_TOT*DIM];
__device__ float g_k  [ROWS_TOT*DIM];
__device__ float g_v  [ROWS_TOT*DIM];
__device__ float g_o  [ROWS_TOT*DIM];
__device__ float g_ffh[ROWS_TOT*FFH];
__device__ float g_qp [BB*HEADS*NN*MF];
__device__ float g_kp [BB*HEADS*NN*MF];
__device__ float g_ctx[BB*HEADS*MF*DH];
__device__ float g_ksum[BB*HEADS*MF];
__device__ int   g_kmax[BB*HEADS];
__device__ float g_pool[BB*DIM];
__device__ float g_z  [BB*DIM];
__device__ float g_z1 [BB*128];

// ---------------- helpers ----------------
__device__ __forceinline__ int f2o(float f) {
    int i = __float_as_int(f);
    return i >= 0 ? i : (i ^ 0x7FFFFFFF);
}
__device__ __forceinline__ float o2f(int i) {
    return __int_as_float(i >= 0 ? i : (i ^ 0x7FFFFFFF));
}
// overflow-safe fast tanh via hardware ex2
__device__ __forceinline__ float tanh_fast(float a) {
    float t = __expf(-2.0f * fabsf(a));      // in (0,1], underflows to 0 for big |a|
    float r = (1.0f - t) / (1.0f + t);
    return copysignf(r, a);
}
__device__ __forceinline__ float gelu_tanh(float x) {
    float x3 = x * x * x;
    return 0.5f * x * (1.0f + tanh_fast(0.7978845608028654f * (x + 0.044715f * x3)));
}

__device__ __forceinline__ float blockReduceSum256(float v) {
    __shared__ float sh[8];
    __syncthreads();
    int lane = threadIdx.x & 31, w = threadIdx.x >> 5;
    #pragma unroll
    for (int o = 16; o; o >>= 1) v += __shfl_xor_sync(0xFFFFFFFFu, v, o);
    if (lane == 0) sh[w] = v;
    __syncthreads();
    if (threadIdx.x == 0) {
        float s = 0.f;
        #pragma unroll
        for (int i = 0; i < 8; i++) s += sh[i];
        sh[0] = s;
    }
    __syncthreads();
    return sh[0];
}

// ---------------- generic tiled SGEMM (double-buffered) ----------------
// C[M,N] = act(A[M,K] @ B[K,N] + bias) + res   (act: 0=none, 1=gelu)
// Requires M%128==0, N%64==0, K%32==0.
__global__ void __launch_bounds__(256) sgemm_kernel(
    const float* __restrict__ A, const float* __restrict__ Bm,
    const float* __restrict__ bias, const float* __restrict__ res,
    float* __restrict__ C, int M, int N, int K, int act)
{
    __shared__ float As[2][16][132];
    __shared__ float Bs[2][16][64];
    const int tid = threadIdx.x;
    const int tx = tid & 15, ty = tid >> 4;
    const int row0 = blockIdx.y * 128, col0 = blockIdx.x * 64;

    float acc[8][4];
    #pragma unroll
    for (int i = 0; i < 8; i++)
        #pragma unroll
        for (int j = 0; j < 4; j++) acc[i][j] = 0.f;

    const int aRow = tid >> 1;
    const int aCol = (tid & 1) * 8;
    const int bCol = tid & 63;
    const int bRow = tid >> 6;      // 0..3

    const float* Aptr = A + (size_t)(row0 + aRow) * K + aCol;
    const float* Bptr = Bm + (size_t)bRow * N + col0 + bCol;

    // preload tile 0
    {
        float4 a0 = *(const float4*)(Aptr);
        float4 a1 = *(const float4*)(Aptr + 4);
        As[0][aCol + 0][aRow] = a0.x; As[0][aCol + 1][aRow] = a0.y;
        As[0][aCol + 2][aRow] = a0.z; As[0][aCol + 3][aRow] = a0.w;
        As[0][aCol + 4][aRow] = a1.x; As[0][aCol + 5][aRow] = a1.y;
        As[0][aCol + 6][aRow] = a1.z; As[0][aCol + 7][aRow] = a1.w;
        #pragma unroll
        for (int r = 0; r < 4; r++)
            Bs[0][bRow + r * 4][bCol] = Bptr[(size_t)(r * 4) * N];
    }
    __syncthreads();

    int buf = 0;
    for (int k0 = 0; k0 < K; k0 += 16) {
        const bool has_next = (k0 + 16) < K;
        float4 na0, na1;
        float nb[4];
        if (has_next) {
            const float* Ap = Aptr + k0 + 16;
            na0 = *(const float4*)(Ap);
            na1 = *(const float4*)(Ap + 4);
            const float* Bp = Bptr + (size_t)(k0 + 16) * N;
            #pragma unroll
            for (int r = 0; r < 4; r++) nb[r] = Bp[(size_t)(r * 4) * N];
        }

        #pragma unroll
        for (int kk = 0; kk < 16; kk++) {
            float4 bA = *(const float4*)&Bs[buf][kk][tx * 4];
            float4 aA = *(const float4*)&As[buf][kk][ty * 8];
            float4 aB = *(const float4*)&As[buf][kk][ty * 8 + 4];
            float ra[8] = {aA.x, aA.y, aA.z, aA.w, aB.x, aB.y, aB.z, aB.w};
            float rb[4] = {bA.x, bA.y, bA.z, bA.w};
            #pragma unroll
            for (int i = 0; i < 8; i++)
                #pragma unroll
                for (int j = 0; j < 4; j++)
                    acc[i][j] = fmaf(ra[i], rb[j], acc[i][j]);
        }

        if (has_next) {
            int nb_ = buf ^ 1;
            As[nb_][aCol + 0][aRow] = na0.x; As[nb_][aCol + 1][aRow] = na0.y;
            As[nb_][aCol + 2][aRow] = na0.z; As[nb_][aCol + 3][aRow] = na0.w;
            As[nb_][aCol + 4][aRow] = na1.x; As[nb_][aCol + 5][aRow] = na1.y;
            As[nb_][aCol + 6][aRow] = na1.z; As[nb_][aCol + 7][aRow] = na1.w;
            #pragma unroll
            for (int r = 0; r < 4; r++)
                Bs[nb_][bRow + r * 4][bCol] = nb[r];
        }
        __syncthreads();
        buf ^= 1;
    }

    #pragma unroll
    for (int i = 0; i < 8; i++) {
        int r = row0 + ty * 8 + i;
        #pragma unroll
        for (int j = 0; j < 4; j++) {
            int c = col0 + tx * 4 + j;
            float v = acc[i][j];
            if (bias) v += bias[c];
            if (act == 1) v = gelu_tanh(v);
            if (res) v += res[(size_t)r * N + c];
            C[(size_t)r * N + c] = v;
        }
    }
}

// ---------------- layernorm (dim 256, 1 row per block) ----------------
__global__ void ln_kernel(const float* __restrict__ x, const float* __restrict__ g,
                          const float* __restrict__ b, float* __restrict__ y)
{
    int row = blockIdx.x;
    int t = threadIdx.x;
    float v = x[(size_t)row * DIM + t];
    float mu = blockReduceSum256(v) * (1.0f / DIM);
    float d = v - mu;
    float var = blockReduceSum256(d * d) * (1.0f / DIM);
    y[(size_t)row * DIM + t] = d * rsqrtf(var + LN_EPS) * g[t] + b[t];
}

// ---------------- FAVOR+ feature kernels ----------------
__global__ void feat_q_kernel(const float* __restrict__ q, const float* __restrict__ proj,
                              float* __restrict__ qp)
{
    __shared__ float qs[16][64];
    __shared__ float dd[16][MF];
    __shared__ int smax[16];
    __shared__ float diag[16];
    const float NORM = 0.35355339059327373f;   // 64^-0.25
    const float RATIO = 0.061314066f;          // 266^-0.5

    int bh = blockIdx.x, b = bh >> 2, head = bh & 3;
    int n0 = blockIdx.y * 16;
    int rows = min(16, NN - n0);
    int tid = threadIdx.x;

    for (int idx = tid; idx < 16 * 64; idx += 256) {
        int r = idx >> 6, d = idx & 63;
        float val = 0.f;
        if (r < rows) val = q[((size_t)(b * NN + n0 + r)) * DIM + head * 64 + d] * NORM;
        qs[r][d] = val;
    }
    __syncthreads();
    if (tid < 16) {
        float s = 0.f;
        #pragma unroll
        for (int d = 0; d < 64; d++) s += qs[tid][d] * qs[tid][d];
        diag[tid] = 0.5f * s;
        smax[tid] = INT_MIN;
    }
    __syncthreads();

    for (int m = tid; m < MF; m += 256) {
        const float* pr = proj + m * DH;
        float acc[16];
        #pragma unroll
        for (int r = 0; r < 16; r++) acc[r] = 0.f;
        #pragma unroll 4
        for (int d = 0; d < 64; d++) {
            float p = pr[d];
            #pragma unroll
            for (int r = 0; r < 16; r++) acc[r] = fmaf(p, qs[r][d], acc[r]);
        }
        #pragma unroll
        for (int r = 0; r < 16; r++) dd[r][m] = acc[r];
        for (int r = 0; r < rows; r++) atomicMax(&smax[r], f2o(acc[r]));
    }
    __syncthreads();

    for (int m = tid; m < MF; m += 256) {
        for (int r = 0; r < rows; r++) {
            float stab = o2f(smax[r]);
            float val = RATIO * (__expf(dd[r][m] - diag[r] - stab) + KEPS);
            qp[((size_t)bh * NN + n0 + r) * MF + m] = val;
        }
    }
}

// pass1: write dd - diag to kp; track global max(dd) per (b,h)
__global__ void feat_k_kernel(const float* __restrict__ k, const float* __restrict__ proj,
                              float* __restrict__ kp, int* __restrict__ kmax)
{
    __shared__ float qs[16][64];
    __shared__ float diag[16];
    __shared__ int bmax;
    const float NORM = 0.35355339059327373f;

    int bh = blockIdx.x, b = bh >> 2, head = bh & 3;
    int n0 = blockIdx.y * 16;
    int rows = min(16, NN - n0);
    int tid = threadIdx.x;

    for (int idx = tid; idx < 16 * 64; idx += 256) {
        int r = idx >> 6, d = idx & 63;
        float val = 0.f;
        if (r < rows) val = k[((size_t)(b * NN + n0 + r)) * DIM + head * 64 + d] * NORM;
        qs[r][d] = val;
    }
    if (tid == 0) bmax = INT_MIN;
    __syncthreads();
    if (tid < 16) {
        float s = 0.f;
        #pragma unroll
        for (int d = 0; d < 64; d++) s += qs[tid][d] * qs[tid][d];
        diag[tid] = 0.5f * s;
    }
    __syncthreads();

    float lmax = -INFINITY;
    for (int m = tid; m < MF; m += 256) {
        const float* pr = proj + m * DH;
        float acc[16];
        #pragma unroll
        for (int r = 0; r < 16; r++) acc[r] = 0.f;
        #pragma unroll 4
        for (int d = 0; d < 64; d++) {
            float p = pr[d];
            #pragma unroll
            for (int r = 0; r < 16; r++) acc[r] = fmaf(p, qs[r][d], acc[r]);
        }
        for (int r = 0; r < rows; r++) {
            lmax = fmaxf(lmax, acc[r]);
            kp[((size_t)bh * NN + n0 + r) * MF + m] = acc[r] - diag[r];
        }
    }
    atomicMax(&bmax, f2o(lmax));
    __syncthreads();
    if (tid == 0) atomicMax(&kmax[bh], bmax);
}

__global__ void kmax_init_kernel(int* __restrict__ kmax) {
    int i = blockIdx.x * blockDim.x + threadIdx.x;
    if (i < BB * HEADS) kmax[i] = INT_MIN;
}

// pass2 fused: kp = ratio*(exp(val - stab) + eps); ksum[m] = sum_n kp[n,m]
__global__ void kexp_ksum_kernel(float* __restrict__ kp, const int* __restrict__ kmax,
                                 float* __restrict__ ksum)
{
    const float RATIO = 0.061314066f;
    int bh = blockIdx.x;
    float stab = o2f(kmax[bh]);
    float* base = kp + (size_t)bh * NN * MF;
    for (int m = threadIdx.x; m < MF; m += blockDim.x) {
        float s0 = 0.f, s1 = 0.f, s2 = 0.f, s3 = 0.f;
        float* p = base + m;
        #pragma unroll 1
        for (int n = 0; n < NN; n += 4) {
            float v0 = RATIO * (__expf(p[(size_t)(n + 0) * MF] - stab) + KEPS);
            float v1 = RATIO * (__expf(p[(size_t)(n + 1) * MF] - stab) + KEPS);
            float v2 = RATIO * (__expf(p[(size_t)(n + 2) * MF] - stab) + KEPS);
            float v3 = RATIO * (__expf(p[(size_t)(n + 3) * MF] - stab) + KEPS);
            p[(size_t)(n + 0) * MF] = v0;
            p[(size_t)(n + 1) * MF] = v1;
            p[(size_t)(n + 2) * MF] = v2;
            p[(size_t)(n + 3) * MF] = v3;
            s0 += v0; s1 += v1; s2 += v2; s3 += v3;
        }
        ksum[bh * MF + m] = (s0 + s1) + (s2 + s3);
    }
}

// context[bh, m, d] = sum_n kp[bh,n,m] * v[b,n,head*64+d]
__global__ void ctx_kernel(const float* __restrict__ kp, const float* __restrict__ v,
                           float* __restrict__ ctx)
{
    extern __shared__ float vs[];  // NN*64
    int bh = blockIdx.x, b = bh >> 2, head = bh & 3;
    int tid = threadIdx.x;
    for (int idx = tid; idx < NN * 64; idx += 256) {
        int n = idx >> 6, d = idx & 63;
        vs[idx] = v[((size_t)(b * NN + n)) * DIM + head * 64 + d];
    }
    __syncthreads();
    int d = tid & 63, mg = tid >> 6;
    for (int m = mg; m < MF; m += 4) {
        const float* kpr = kp + (size_t)bh * NN * MF + m;
        float a0 = 0.f, a1 = 0.f, a2 = 0.f, a3 = 0.f;
        #pragma unroll 1
        for (int n = 0; n < NN; n += 4) {
            a0 = fmaf(kpr[(size_t)(n + 0) * MF], vs[(n + 0) * 64 + d], a0);
            a1 = fmaf(kpr[(size_t)(n + 1) * MF], vs[(n + 1) * 64 + d], a1);
            a2 = fmaf(kpr[(size_t)(n + 2) * MF], vs[(n + 2) * 64 + d], a2);
            a3 = fmaf(kpr[(size_t)(n + 3) * MF], vs[(n + 3) * 64 + d], a3);
        }
        ctx[((size_t)bh * MF + m) * 64 + d] = (a0 + a1) + (a2 + a3);
    }
}

// o[b,n,head*64+d] = (qp[n,:] . ctx[:,d]) / (qp[n,:] . ksum)
__global__ void attnout_kernel(const float* __restrict__ qp, const float* __restrict__ ctx,
                               const float* __restrict__ ksum, float* __restrict__ o)
{
    extern __shared__ float cs[];           // MF*64 + MF
    float* ks = cs + MF * 64;
    int bh = blockIdx.x, b = bh >> 2, head = bh & 3;
    int tid = threadIdx.x;
    for (int idx = tid; idx < MF * 64; idx += 256) cs[idx] = ctx[(size_t)bh * MF * 64 + idx];
    for (int m = tid; m < MF; m += 256) ks[m] = ksum[bh * MF + m];
    __syncthreads();
    int d = tid & 63, ng = tid >> 6;
    for (int n = ng; n < NN; n += 4) {
        const float* qpr = qp + ((size_t)bh * NN + n) * MF;
        float a0 = 0.f, a1 = 0.f, de0 = 0.f, de1 = 0.f;
        #pragma unroll 1
        for (int m = 0; m < MF; m += 2) {
            float q0 = qpr[m], q1 = qpr[m + 1];
            a0 = fmaf(q0, cs[m * 64 + d], a0);
            de0 = fmaf(q0, ks[m], de0);
            a1 = fmaf(q1, cs[(m + 1) * 64 + d], a1);
            de1 = fmaf(q1, ks[m + 1], de1);
        }
        o[((size_t)(b * NN + n)) * DIM + head * 64 + d] = (a0 + a1) / (de0 + de1);
    }
}

// ---------------- pooling & head ----------------
__global__ void pool_kernel(const float* __restrict__ h, float* __restrict__ pooled)
{
    int b = blockIdx.x, c = threadIdx.x;
    const float* p = h + (size_t)b * NN * DIM + c;
    float s0 = 0.f, s1 = 0.f, s2 = 0.f, s3 = 0.f;
    for (int n = 0; n < 300; n += 4) {
        s0 += p[(size_t)(n + 0) * DIM];
        s1 += p[(size_t)(n + 1) * DIM];
        s2 += p[(size_t)(n + 2) * DIM];
        s3 += p[(size_t)(n + 3) * DIM];
    }
    pooled[b * DIM + c] = ((s0 + s1) + (s2 + s3)) * (1.0f / NN);
}

__global__ void head1_kernel(const float* __restrict__ z, const float* __restrict__ w,
                             const float* __restrict__ bias, float* __restrict__ z1)
{
    __shared__ float zs[DIM];
    int b = blockIdx.x, j = threadIdx.x;   // 128 threads
    for (int c = j; c < DIM; c += 128) zs[c] = z[b * DIM + c];
    __syncthreads();
    float s0 = 0.f, s1 = 0.f, s2 = 0.f, s3 = 0.f;
    #pragma unroll 1
    for (int c = 0; c < DIM; c += 4) {
        s0 = fmaf(zs[c + 0], w[(c + 0) * 128 + j], s0);
        s1 = fmaf(zs[c + 1], w[(c + 1) * 128 + j], s1);
        s2 = fmaf(zs[c + 2], w[(c + 2) * 128 + j], s2);
        s3 = fmaf(zs[c + 3], w[(c + 3) * 128 + j], s3);
    }
    float s = ((s0 + s1) + (s2 + s3)) + bias[j];
    z1[b * 128 + j] = fmaxf(s, 0.f);
}

__global__ void head2_kernel(const float* __restrict__ z1, const float* __restrict__ w,
                             const float* __restrict__ bias, float* __restrict__ out)
{
    __shared__ float sh[4];
    int b = blockIdx.x, j = threadIdx.x;   // 128 threads
    float s = z1[b * 128 + j] * w[j];
    #pragma unroll
    for (int o = 16; o; o >>= 1) s += __shfl_xor_sync(0xFFFFFFFFu, s, o);
    if ((j & 31) == 0) sh[j >> 5] = s;
    __syncthreads();
    if (j == 0) {
        float t = sh[0] + sh[1] + sh[2] + sh[3] + bias[0];
        out[b] = 1.0f / (1.0f + __expf(-t));
    }
}

// ---------------- host ----------------
static float* symaddr(const void* sym) {
    void* p = nullptr;
    cudaGetSymbolAddress(&p, sym);
    return (float*)p;
}

extern "C" void kernel_launch(void* const* d_in, const int* in_sizes, int n_in,
                              void* d_out, int out_size)
{
    const float* x     = (const float*)d_in[0];
    const float* w_in  = (const float*)d_in[1];
    const float* b_in  = (const float*)d_in[2];
    const float* proj  = (const float*)d_in[3];
    const float* ln1_g = (const float*)d_in[4];
    const float* ln1_b = (const float*)d_in[5];
    const float* wq    = (const float*)d_in[6];
    const float* wk    = (const float*)d_in[7];
    const float* wv    = (const float*)d_in[8];
    const float* wo    = (const float*)d_in[9];
    const float* bo    = (const float*)d_in[10];
    const float* ln2_g = (const float*)d_in[11];
    const float* ln2_b = (const float*)d_in[12];
    const float* w1    = (const float*)d_in[13];
    const float* b1    = (const float*)d_in[14];
    const float* w2    = (const float*)d_in[15];
    const float* b2    = (const float*)d_in[16];
    const float* hln_g = (const float*)d_in[17];
    const float* hln_b = (const float*)d_in[18];
    const float* wh1   = (const float*)d_in[19];
    const float* bh1   = (const float*)d_in[20];
    const float* wh2   = (const float*)d_in[21];
    const float* bh2   = (const float*)d_in[22];
    float* out = (float*)d_out;

    float* h   = symaddr(g_h);
    float* y   = symaddr(g_y);
    float* q   = symaddr(g_q);
    float* k   = symaddr(g_k);
    float* v   = symaddr(g_v);
    float* o   = symaddr(g_o);
    float* ffh = symaddr(g_ffh);
    float* qp  = symaddr(g_qp);
    float* kp  = symaddr(g_kp);
    float* ctx = symaddr(g_ctx);
    float* ksm = symaddr(g_ksum);
    int*   kmx = (int*)symaddr(g_kmax);
    float* pool = symaddr(g_pool);
    float* z   = symaddr(g_z);
    float* z1  = symaddr(g_z1);

    const int ctx_smem = NN * 64 * 4;                 // 76800 B
    const int out_smem = (MF * 64 + MF) * 4;          // 69160 B
    cudaFuncSetAttribute(ctx_kernel,     cudaFuncAttributeMaxDynamicSharedMemorySize, ctx_smem);
    cudaFuncSetAttribute(attnout_kernel, cudaFuncAttributeMaxDynamicSharedMemorySize, out_smem);

    dim3 blk(256);
    dim3 gN256(DIM / 64, ROWS_TOT / 128);     // N=256
    dim3 gN1024(FFH / 64, ROWS_TOT / 128);    // N=1024
    dim3 featGrid(BB * HEADS, (NN + 15) / 16);

    // h = x @ w_in + b_in
    sgemm_kernel<<<gN256, blk>>>(x, w_in, b_in, nullptr, h, ROWS_TOT, DIM, IN_DIM, 0);

    for (int l = 0; l < 2; l++) {
        const float* projl = proj + (size_t)l * MF * DH;
        // --- attention ---
        ln_kernel<<<ROWS_TOT, 256>>>(h, ln1_g + l * DIM, ln1_b + l * DIM, y);
        sgemm_kernel<<<gN256, blk>>>(y, wq + (size_t)l * DIM * DIM, nullptr, nullptr, q, ROWS_TOT, DIM, DIM, 0);
        sgemm_kernel<<<gN256, blk>>>(y, wk + (size_t)l * DIM * DIM, nullptr, nullptr, k, ROWS_TOT, DIM, DIM, 0);
        sgemm_kernel<<<gN256, blk>>>(y, wv + (size_t)l * DIM * DIM, nullptr, nullptr, v, ROWS_TOT, DIM, DIM, 0);

        kmax_init_kernel<<<1, 1024>>>(kmx);
        feat_q_kernel<<<featGrid, blk>>>(q, projl, qp);
        feat_k_kernel<<<featGrid, blk>>>(k, projl, kp, kmx);
        kexp_ksum_kernel<<<BB * HEADS, blk>>>(kp, kmx, ksm);
        ctx_kernel<<<BB * HEADS, blk, ctx_smem>>>(kp, v, ctx);
        attnout_kernel<<<BB * HEADS, blk, out_smem>>>(qp, ctx, ksm, o);

        sgemm_kernel<<<gN256, blk>>>(o, wo + (size_t)l * DIM * DIM, bo + l * DIM, h, h, ROWS_TOT, DIM, DIM, 0);

        // --- FFN ---
        ln_kernel<<<ROWS_TOT, 256>>>(h, ln2_g + l * DIM, ln2_b + l * DIM, y);
        sgemm_kernel<<<gN1024, blk>>>(y, w1 + (size_t)l * DIM * FFH, b1 + l * FFH, nullptr, ffh, ROWS_TOT, FFH, DIM, 1);
        sgemm_kernel<<<gN256, blk>>>(ffh, w2 + (size_t)l * FFH * DIM, b2 + l * DIM, h, h, ROWS_TOT, DIM, FFH, 0);
    }

    pool_kernel<<<BB, 256>>>(h, pool);
    ln_kernel<<<BB, 256>>>(pool, hln_g, hln_b, z);
    head1_kernel<<<BB, 128>>>(z, wh1, bh1, z1);
    head2_kernel<<<BB, 128>>>(z1, wh2, bh2, out);
}

// round 4
// speedup vs baseline: 1.5197x; 1.5009x over previous
#include <cuda_runtime.h>
#include <cuda_bf16.h>
#include <math.h>
#include <limits.h>
#include <stdint.h>

// ---------------- problem constants ----------------
#define BB 256
#define NN 300
#define IN_DIM 1280
#define DIM 256
#define HEADS 4
#define DH 64
#define MF 266            // NB_FEAT
#define MP 320            // padded feature dim (multiple of 64)
#define FFH 1024
#define ROWS_TOT (BB*NN)  // 76800
#define RH (ROWS_TOT*HEADS) // 307200

#define LN_EPS 1e-5f
#define KEPS 1e-4f
#define RATIO 0.061314066f          // 266^-0.5
#define NORM 0.35355339059327373f   // 64^-0.25

// ---------------- scratch ----------------
__device__ float          g_h   [ROWS_TOT*DIM];
__device__ __nv_bfloat16  g_yb  [ROWS_TOT*DIM];
__device__ float          g_q   [ROWS_TOT*DIM];
__device__ float          g_k   [ROWS_TOT*DIM];
__device__ float          g_v   [ROWS_TOT*DIM];
__device__ __nv_bfloat16  g_qb  [ROWS_TOT*DIM];
__device__ __nv_bfloat16  g_kb  [ROWS_TOT*DIM];
__device__ __nv_bfloat16  g_ob  [ROWS_TOT*DIM];
__device__ __nv_bfloat16  g_ffhb[ROWS_TOT*FFH];
__device__ __nv_bfloat16  g_xb  [ROWS_TOT*IN_DIM];
__device__ float          g_qp  [(size_t)RH*MP];
__device__ float          g_kp  [(size_t)RH*MP];
__device__ float          g_ctx [BB*HEADS*MF*DH];
__device__ float          g_ksum[BB*HEADS*MF];
__device__ int            g_kmax[BB*HEADS];
__device__ float          g_pool[BB*DIM];
__device__ float          g_z   [BB*DIM];
__device__ float          g_z1  [BB*128];
__device__ __nv_bfloat16  g_pTb [MP*64];
// transposed bf16 weights
__device__ __nv_bfloat16  g_wInT[DIM*IN_DIM];
__device__ __nv_bfloat16  g_wqT [2][DIM*DIM];
__device__ __nv_bfloat16  g_wkT [2][DIM*DIM];
__device__ __nv_bfloat16  g_wvT [2][DIM*DIM];
__device__ __nv_bfloat16  g_woT [2][DIM*DIM];
__device__ __nv_bfloat16  g_w1T [2][FFH*DIM];
__device__ __nv_bfloat16  g_w2T [2][DIM*FFH];

// ---------------- helpers ----------------
__device__ __forceinline__ int f2o(float f) {
    int i = __float_as_int(f);
    return i >= 0 ? i : (i ^ 0x7FFFFFFF);
}
__device__ __forceinline__ float o2f(int i) {
    return __int_as_float(i >= 0 ? i : (i ^ 0x7FFFFFFF));
}
__device__ __forceinline__ float tanh_fast(float a) {
    float t = __expf(-2.0f * fabsf(a));
    float r = (1.0f - t) / (1.0f + t);
    return copysignf(r, a);
}
__device__ __forceinline__ float gelu_tanh(float x) {
    float x3 = x * x * x;
    return 0.5f * x * (1.0f + tanh_fast(0.7978845608028654f * (x + 0.044715f * x3)));
}
__device__ __forceinline__ float blockReduceSum256(float v) {
    __shared__ float sh[8];
    __syncthreads();
    int lane = threadIdx.x & 31, w = threadIdx.x >> 5;
    #pragma unroll
    for (int o = 16; o; o >>= 1) v += __shfl_xor_sync(0xFFFFFFFFu, v, o);
    if (lane == 0) sh[w] = v;
    __syncthreads();
    if (threadIdx.x == 0) {
        float s = 0.f;
        #pragma unroll
        for (int i = 0; i < 8; i++) s += sh[i];
        sh[0] = s;
    }
    __syncthreads();
    return sh[0];
}
__device__ __forceinline__ uint32_t smem_u32(const void* p) {
    uint32_t a;
    asm("{ .reg .u64 t; cvta.to.shared.u64 t, %1; cvt.u32.u64 %0, t; }" : "=r"(a) : "l"(p));
    return a;
}

#define SWZ(off) ((off) ^ (((off) >> 3) & 0x70))

__device__ __forceinline__ void ldmatrix4(uint32_t* r, uint32_t addr) {
    asm volatile("ldmatrix.sync.aligned.m8n8.x4.shared.b16 {%0,%1,%2,%3}, [%4];"
        : "=r"(r[0]), "=r"(r[1]), "=r"(r[2]), "=r"(r[3]) : "r"(addr));
}
__device__ __forceinline__ void mma16816(float* c, const uint32_t* a, uint32_t b0, uint32_t b1) {
    asm volatile(
        "mma.sync.aligned.m16n8k16.row.col.f32.bf16.bf16.f32 "
        "{%0,%1,%2,%3}, {%4,%5,%6,%7}, {%8,%9}, {%0,%1,%2,%3};"
        : "+f"(c[0]), "+f"(c[1]), "+f"(c[2]), "+f"(c[3])
        : "r"(a[0]), "r"(a[1]), "r"(a[2]), "r"(a[3]), "r"(b0), "r"(b1));
}

// ---------------- bf16 HMMA GEMM ----------------
// C = act(A[M,K](bf16) @ Bt[N,K](bf16)^T + bias) (+res). M%128==0, N%64==0, K%64==0.
#define TG_SMEM_BYTES 49152

__global__ void __launch_bounds__(256) tgemm_kernel(
    const __nv_bfloat16* __restrict__ A, const __nv_bfloat16* __restrict__ Bt,
    const float* __restrict__ bias, const float* __restrict__ res,
    float* __restrict__ Cf, __nv_bfloat16* __restrict__ Cb,
    int M, int N, int K, int act)
{
    extern __shared__ __nv_bfloat16 sm[];
    // As: 2 bufs x 128x64 (16384 B each); Bs: 2 bufs x 64x64 (8192 B each)
    const uint32_t aBase = smem_u32(sm);
    const uint32_t bBase = aBase + 32768;
    char* smc = (char*)sm;

    const int tid = threadIdx.x;
    const int wid = tid >> 5, lane = tid & 31;
    const int wm = wid & 3, wn = wid >> 2;        // warp grid 4 (M) x 2 (N)
    const int row0 = blockIdx.y * 128, col0 = blockIdx.x * 64;
    const int tileid = lane >> 3, rit = lane & 7; // ldmatrix addressing
    const int gid = lane >> 2, tig = lane & 3;    // mma C fragment

    float acc[2][4][4];
    #pragma unroll
    for (int mt = 0; mt < 2; mt++)
        #pragma unroll
        for (int j = 0; j < 4; j++)
            #pragma unroll
            for (int r = 0; r < 4; r++) acc[mt][j][r] = 0.f;

    const int nch = K >> 6;

    // ---- load chunk 0 directly to smem buf 0 ----
    {
        #pragma unroll
        for (int i = 0; i < 4; i++) {
            int lin = tid + i * 256;
            int r = lin >> 3, c16 = lin & 7;
            uint4 d = *(const uint4*)(A + (size_t)(row0 + r) * K + c16 * 8);
            *(uint4*)(smc + SWZ(r * 128 + c16 * 16)) = d;
        }
        #pragma unroll
        for (int i = 0; i < 2; i++) {
            int lin = tid + i * 256;
            int r = lin >> 3, c16 = lin & 7;
            uint4 d = *(const uint4*)(Bt + (size_t)(col0 + r) * K + c16 * 8);
            *(uint4*)(smc + 32768 + SWZ(r * 128 + c16 * 16)) = d;
        }
    }
    __syncthreads();

    for (int c = 0; c < nch; c++) {
        const int buf = c & 1;
        const bool has_next = (c + 1) < nch;
        uint4 pa[4], pb[2];
        if (has_next) {
            const int k0 = (c + 1) << 6;
            #pragma unroll
            for (int i = 0; i < 4; i++) {
                int lin = tid + i * 256;
                int r = lin >> 3, c16 = lin & 7;
                pa[i] = *(const uint4*)(A + (size_t)(row0 + r) * K + k0 + c16 * 8);
            }
            #pragma unroll
            for (int i = 0; i < 2; i++) {
                int lin = tid + i * 256;
                int r = lin >> 3, c16 = lin & 7;
                pb[i] = *(const uint4*)(Bt + (size_t)(col0 + r) * K + k0 + c16 * 8);
            }
        }

        // ---- compute on buf ----
        const uint32_t aB = aBase + buf * 16384;
        const uint32_t bB = bBase + buf * 8192;
        #pragma unroll
        for (int kk = 0; kk < 4; kk++) {
            uint32_t af[2][4];
            #pragma unroll
            for (int mt = 0; mt < 2; mt++) {
                int off = (wm * 32 + mt * 16 + (tileid & 1) * 8 + rit) * 128
                          + kk * 32 + (tileid >> 1) * 16;
                ldmatrix4(af[mt], aB + SWZ(off));
            }
            uint32_t bf[2][4];
            #pragma unroll
            for (int nt = 0; nt < 2; nt++) {
                int off = (wn * 32 + nt * 16 + (tileid & 1) * 8 + rit) * 128
                          + kk * 32 + (tileid >> 1) * 16;
                ldmatrix4(bf[nt], bB + SWZ(off));
            }
            #pragma unroll
            for (int mt = 0; mt < 2; mt++)
                #pragma unroll
                for (int j = 0; j < 4; j++) {
                    int nt = j >> 1, sel = j & 1;
                    mma16816(acc[mt][j], af[mt], bf[nt][sel], bf[nt][2 + sel]);
                }
        }

        if (has_next) {
            const int nb = buf ^ 1;
            #pragma unroll
            for (int i = 0; i < 4; i++) {
                int lin = tid + i * 256;
                int r = lin >> 3, c16 = lin & 7;
                *(uint4*)(smc + nb * 16384 + SWZ(r * 128 + c16 * 16)) = pa[i];
            }
            #pragma unroll
            for (int i = 0; i < 2; i++) {
                int lin = tid + i * 256;
                int r = lin >> 3, c16 = lin & 7;
                *(uint4*)(smc + 32768 + nb * 8192 + SWZ(r * 128 + c16 * 16)) = pb[i];
            }
        }
        __syncthreads();
    }

    // ---- epilogue ----
    #pragma unroll
    for (int mt = 0; mt < 2; mt++) {
        #pragma unroll
        for (int j = 0; j < 4; j++) {
            #pragma unroll
            for (int half = 0; half < 2; half++) {
                int r = row0 + wm * 32 + mt * 16 + gid + half * 8;
                int cidx = col0 + wn * 32 + j * 8 + tig * 2;
                float v0 = acc[mt][j][half * 2 + 0];
                float v1 = acc[mt][j][half * 2 + 1];
                if (bias) { v0 += bias[cidx]; v1 += bias[cidx + 1]; }
                if (act == 1) { v0 = gelu_tanh(v0); v1 = gelu_tanh(v1); }
                if (res) {
                    float2 r2 = *(const float2*)(res + (size_t)r * N + cidx);
                    v0 += r2.x; v1 += r2.y;
                }
                if (Cf) *(float2*)(Cf + (size_t)r * N + cidx) = make_float2(v0, v1);
                if (Cb) *(__nv_bfloat162*)(Cb + (size_t)r * N + cidx) = __floats2bfloat162_rn(v0, v1);
            }
        }
    }
}

// ---------------- prep kernels ----------------
__global__ void f2b_kernel(const float* __restrict__ a, __nv_bfloat16* __restrict__ b, size_t n) {
    size_t i = (size_t)blockIdx.x * blockDim.x + threadIdx.x;
    if (i < n) b[i] = __float2bfloat16(a[i]);
}

__global__ void wtrans_kernel(const float* __restrict__ W, __nv_bfloat16* __restrict__ Wt,
                              int K, int N) {
    __shared__ float t[32][33];
    int k0 = blockIdx.y * 32, n0 = blockIdx.x * 32;
    int tx = threadIdx.x, ty = threadIdx.y;   // 32 x 8
    #pragma unroll
    for (int i = 0; i < 32; i += 8)
        t[ty + i][tx] = W[(size_t)(k0 + ty + i) * N + n0 + tx];
    __syncthreads();
    #pragma unroll
    for (int i = 0; i < 32; i += 8)
        Wt[(size_t)(n0 + ty + i) * K + k0 + tx] = __float2bfloat16(t[tx][ty + i]);
}

__global__ void projb_kernel(const float* __restrict__ proj, __nv_bfloat16* __restrict__ pTb) {
    int i = blockIdx.x * 256 + threadIdx.x;
    if (i >= MP * 64) return;
    int m = i >> 6, d = i & 63;
    pTb[i] = __float2bfloat16((m < MF) ? proj[m * 64 + d] * NORM : 0.f);
}

// ---------------- layernorm ----------------
__global__ void ln_bf16_kernel(const float* __restrict__ x, const float* __restrict__ g,
                               const float* __restrict__ b, __nv_bfloat16* __restrict__ y)
{
    int row = blockIdx.x;
    int t = threadIdx.x;
    float v = x[(size_t)row * DIM + t];
    float mu = blockReduceSum256(v) * (1.0f / DIM);
    float d = v - mu;
    float var = blockReduceSum256(d * d) * (1.0f / DIM);
    y[(size_t)row * DIM + t] = __float2bfloat16(d * rsqrtf(var + LN_EPS) * g[t] + b[t]);
}

__global__ void ln_f32_kernel(const float* __restrict__ x, const float* __restrict__ g,
                              const float* __restrict__ b, float* __restrict__ y)
{
    int row = blockIdx.x;
    int t = threadIdx.x;
    float v = x[(size_t)row * DIM + t];
    float mu = blockReduceSum256(v) * (1.0f / DIM);
    float d = v - mu;
    float var = blockReduceSum256(d * d) * (1.0f / DIM);
    y[(size_t)row * DIM + t] = d * rsqrtf(var + LN_EPS) * g[t] + b[t];
}

// ---------------- FAVOR+ passes ----------------
// qp/kp rows: w = (b*NN+n)*HEADS + h, stride MP. q viewed as [RH][64].
__global__ void qexp_kernel(const float* __restrict__ q, float* __restrict__ dd)
{
    int w = (blockIdx.x * 256 + threadIdx.x) >> 5;
    int lane = threadIdx.x & 31;
    if (w >= RH) return;
    const float* qr = q + (size_t)w * 64;
    float a = qr[lane], b = qr[lane + 32];
    float s = a * a + b * b;
    #pragma unroll
    for (int o = 16; o; o >>= 1) s += __shfl_xor_sync(0xFFFFFFFFu, s, o);
    float diag = 0.0625f * s;   // 0.5 * NORM^2
    float* row = dd + (size_t)w * MP;
    float vv[9], mx = -1e30f;
    #pragma unroll
    for (int i = 0; i < 9; i++) {
        int m = lane + 32 * i;
        vv[i] = (m < MF) ? row[m] : -1e30f;
        mx = fmaxf(mx, vv[i]);
    }
    #pragma unroll
    for (int o = 16; o; o >>= 1) mx = fmaxf(mx, __shfl_xor_sync(0xFFFFFFFFu, mx, o));
    #pragma unroll
    for (int i = 0; i < 9; i++) {
        int m = lane + 32 * i;
        if (m < MF) row[m] = RATIO * (__expf(vv[i] - diag - mx) + KEPS);
    }
}

__global__ void kmax_init_kernel(int* __restrict__ kmax) {
    int i = blockIdx.x * blockDim.x + threadIdx.x;
    if (i < BB * HEADS) kmax[i] = INT_MIN;
}

__global__ void kmax_kernel(const float* __restrict__ dd, int* __restrict__ kmax)
{
    int w = (blockIdx.x * 256 + threadIdx.x) >> 5;
    int lane = threadIdx.x & 31;
    if (w >= RH) return;
    const float* row = dd + (size_t)w * MP;
    float mx = -1e30f;
    #pragma unroll
    for (int i = 0; i < 9; i++) {
        int m = lane + 32 * i;
        if (m < MF) mx = fmaxf(mx, row[m]);
    }
    #pragma unroll
    for (int o = 16; o; o >>= 1) mx = fmaxf(mx, __shfl_xor_sync(0xFFFFFFFFu, mx, o));
    if (lane == 0) {
        int bh = (w / (NN * HEADS)) * HEADS + (w & 3);
        atomicMax(&kmax[bh], f2o(mx));
    }
}

__global__ void kexp_kernel(const float* __restrict__ k, float* __restrict__ dd,
                            const int* __restrict__ kmax)
{
    int w = (blockIdx.x * 256 + threadIdx.x) >> 5;
    int lane = threadIdx.x & 31;
    if (w >= RH) return;
    const float* kr = k + (size_t)w * 64;
    float a = kr[lane], b = kr[lane + 32];
    float s = a * a + b * b;
    #pragma unroll
    for (int o = 16; o; o >>= 1) s += __shfl_xor_sync(0xFFFFFFFFu, s, o);
    float diag = 0.0625f * s;
    int bh = (w / (NN * HEADS)) * HEADS + (w & 3);
    float stab = o2f(kmax[bh]);
    float* row = dd + (size_t)w * MP;
    #pragma unroll
    for (int i = 0; i < 9; i++) {
        int m = lane + 32 * i;
        if (m < MF) row[m] = RATIO * (__expf(row[m] - diag - stab) + KEPS);
    }
}

__global__ void ksum_kernel(const float* __restrict__ kp, float* __restrict__ ksum)
{
    int bh = blockIdx.x, b = bh >> 2, h = bh & 3;
    for (int m = threadIdx.x; m < MF; m += 256) {
        const float* base = kp + ((size_t)(b * NN) * HEADS + h) * MP + m;
        float s0 = 0.f, s1 = 0.f, s2 = 0.f, s3 = 0.f;
        #pragma unroll 1
        for (int n = 0; n < NN; n += 4) {
            s0 += base[(size_t)(n + 0) * HEADS * MP];
            s1 += base[(size_t)(n + 1) * HEADS * MP];
            s2 += base[(size_t)(n + 2) * HEADS * MP];
            s3 += base[(size_t)(n + 3) * HEADS * MP];
        }
        ksum[bh * MF + m] = (s0 + s1) + (s2 + s3);
    }
}

// ctx[bh, m, d] = sum_n kp[(b,n,h), m] * v[b, n, h*64+d]
__global__ void ctx_kernel(const float* __restrict__ kp, const float* __restrict__ v,
                           float* __restrict__ ctx)
{
    extern __shared__ float vs[];  // NN*64
    int bh = blockIdx.x, b = bh >> 2, h = bh & 3;
    int tid = threadIdx.x;
    for (int idx = tid; idx < NN * 64; idx += 256) {
        int n = idx >> 6, d = idx & 63;
        vs[idx] = v[((size_t)(b * NN + n)) * DIM + h * 64 + d];
    }
    __syncthreads();
    int d = tid & 63, mg = tid >> 6;
    const float* kbase = kp + ((size_t)(b * NN) * HEADS + h) * MP;
    for (int m0 = mg * 4; m0 < MF; m0 += 16) {
        float a0 = 0.f, a1 = 0.f, a2 = 0.f, a3 = 0.f;
        #pragma unroll 1
        for (int n = 0; n < NN; n++) {
            float vv = vs[n * 64 + d];
            float4 k4 = *(const float4*)(kbase + (size_t)n * HEADS * MP + m0);
            a0 = fmaf(k4.x, vv, a0);
            a1 = fmaf(k4.y, vv, a1);
            a2 = fmaf(k4.z, vv, a2);
            a3 = fmaf(k4.w, vv, a3);
        }
        float accs[4] = {a0, a1, a2, a3};
        #pragma unroll
        for (int j = 0; j < 4; j++)
            if (m0 + j < MF)
                ctx[((size_t)bh * MF + m0 + j) * 64 + d] = accs[j];
    }
}

// o[b,n,h*64+d] = (qp . ctx[:,d]) / (qp . ksum)   (bf16 out)
#define CSM 268
__global__ void attnout_kernel(const float* __restrict__ qp, const float* __restrict__ ctx,
                               const float* __restrict__ ksum, __nv_bfloat16* __restrict__ o)
{
    extern __shared__ float cs[];           // CSM*64 + CSM
    float* ks = cs + CSM * 64;
    int bh = blockIdx.x, b = bh >> 2, h = bh & 3;
    int tid = threadIdx.x;
    for (int idx = tid; idx < MF * 64; idx += 256) {
        cs[idx] = ctx[(size_t)bh * MF * 64 + idx];
    }
    for (int idx = MF * 64 + tid; idx < CSM * 64; idx += 256) cs[idx] = 0.f;
    for (int m = tid; m < CSM; m += 256) ks[m] = (m < MF) ? ksum[bh * MF + m] : 0.f;
    __syncthreads();
    int d = tid & 63, ng = tid >> 6;
    for (int n = ng; n < NN; n += 4) {
        const float* qrow = qp + ((size_t)((b * NN + n) * HEADS) + h) * MP;
        float a0 = 0.f, a1 = 0.f, de0 = 0.f, de1 = 0.f;
        #pragma unroll 1
        for (int m0 = 0; m0 < CSM; m0 += 4) {
            float4 q4 = *(const float4*)(qrow + m0);
            a0 = fmaf(q4.x, cs[m0 * 64 + d], a0);
            de0 = fmaf(q4.x, ks[m0], de0);
            a1 = fmaf(q4.y, cs[(m0 + 1) * 64 + d], a1);
            de1 = fmaf(q4.y, ks[m0 + 1], de1);
            a0 = fmaf(q4.z, cs[(m0 + 2) * 64 + d], a0);
            de0 = fmaf(q4.z, ks[m0 + 2], de0);
            a1 = fmaf(q4.w, cs[(m0 + 3) * 64 + d], a1);
            de1 = fmaf(q4.w, ks[m0 + 3], de1);
        }
        o[((size_t)(b * NN + n)) * DIM + h * 64 + d] =
            __float2bfloat16((a0 + a1) / (de0 + de1));
    }
}

// ---------------- pooling & head ----------------
__global__ void pool_kernel(const float* __restrict__ h, float* __restrict__ pooled)
{
    int b = blockIdx.x, c = threadIdx.x;
    const float* p = h + (size_t)b * NN * DIM + c;
    float s0 = 0.f, s1 = 0.f, s2 = 0.f, s3 = 0.f;
    for (int n = 0; n < NN; n += 4) {
        s0 += p[(size_t)(n + 0) * DIM];
        s1 += p[(size_t)(n + 1) * DIM];
        s2 += p[(size_t)(n + 2) * DIM];
        s3 += p[(size_t)(n + 3) * DIM];
    }
    pooled[b * DIM + c] = ((s0 + s1) + (s2 + s3)) * (1.0f / NN);
}

__global__ void head1_kernel(const float* __restrict__ z, const float* __restrict__ w,
                             const float* __restrict__ bias, float* __restrict__ z1)
{
    __shared__ float zs[DIM];
    int b = blockIdx.x, j = threadIdx.x;
    for (int c = j; c < DIM; c += 128) zs[c] = z[b * DIM + c];
    __syncthreads();
    float s0 = 0.f, s1 = 0.f, s2 = 0.f, s3 = 0.f;
    #pragma unroll 1
    for (int c = 0; c < DIM; c += 4) {
        s0 = fmaf(zs[c + 0], w[(c + 0) * 128 + j], s0);
        s1 = fmaf(zs[c + 1], w[(c + 1) * 128 + j], s1);
        s2 = fmaf(zs[c + 2], w[(c + 2) * 128 + j], s2);
        s3 = fmaf(zs[c + 3], w[(c + 3) * 128 + j], s3);
    }
    z1[b * 128 + j] = fmaxf(((s0 + s1) + (s2 + s3)) + bias[j], 0.f);
}

__global__ void head2_kernel(const float* __restrict__ z1, const float* __restrict__ w,
                             const float* __restrict__ bias, float* __restrict__ out)
{
    __shared__ float sh[4];
    int b = blockIdx.x, j = threadIdx.x;
    float s = z1[b * 128 + j] * w[j];
    #pragma unroll
    for (int o = 16; o; o >>= 1) s += __shfl_xor_sync(0xFFFFFFFFu, s, o);
    if ((j & 31) == 0) sh[j >> 5] = s;
    __syncthreads();
    if (j == 0) {
        float t = sh[0] + sh[1] + sh[2] + sh[3] + bias[0];
        out[b] = 1.0f / (1.0f + __expf(-t));
    }
}

// ---------------- host ----------------
template <typename T> static T* symaddr(const void* sym) {
    void* p = nullptr;
    cudaGetSymbolAddress(&p, sym);
    return (T*)p;
}

extern "C" void kernel_launch(void* const* d_in, const int* in_sizes, int n_in,
                              void* d_out, int out_size)
{
    const float* x     = (const float*)d_in[0];
    const float* w_in  = (const float*)d_in[1];
    const float* b_in  = (const float*)d_in[2];
    const float* proj  = (const float*)d_in[3];
    const float* ln1_g = (const float*)d_in[4];
    const float* ln1_b = (const float*)d_in[5];
    const float* wq    = (const float*)d_in[6];
    const float* wk    = (const float*)d_in[7];
    const float* wv    = (const float*)d_in[8];
    const float* wo    = (const float*)d_in[9];
    const float* bo    = (const float*)d_in[10];
    const float* ln2_g = (const float*)d_in[11];
    const float* ln2_b = (const float*)d_in[12];
    const float* w1    = (const float*)d_in[13];
    const float* b1    = (const float*)d_in[14];
    const float* w2    = (const float*)d_in[15];
    const float* b2    = (const float*)d_in[16];
    const float* hln_g = (const float*)d_in[17];
    const float* hln_b = (const float*)d_in[18];
    const float* wh1   = (const float*)d_in[19];
    const float* bh1   = (const float*)d_in[20];
    const float* wh2   = (const float*)d_in[21];
    const float* bh2   = (const float*)d_in[22];
    float* out = (float*)d_out;

    float* h    = symaddr<float>(g_h);
    __nv_bfloat16* yb   = symaddr<__nv_bfloat16>(g_yb);
    float* q    = symaddr<float>(g_q);
    float* k    = symaddr<float>(g_k);
    float* v    = symaddr<float>(g_v);
    __nv_bfloat16* qb   = symaddr<__nv_bfloat16>(g_qb);
    __nv_bfloat16* kb   = symaddr<__nv_bfloat16>(g_kb);
    __nv_bfloat16* ob   = symaddr<__nv_bfloat16>(g_ob);
    __nv_bfloat16* ffhb = symaddr<__nv_bfloat16>(g_ffhb);
    __nv_bfloat16* xb   = symaddr<__nv_bfloat16>(g_xb);
    float* qp   = symaddr<float>(g_qp);
    float* kp   = symaddr<float>(g_kp);
    float* ctx  = symaddr<float>(g_ctx);
    float* ksm  = symaddr<float>(g_ksum);
    int*   kmx  = symaddr<int>(g_kmax);
    float* pool = symaddr<float>(g_pool);
    float* z    = symaddr<float>(g_z);
    float* z1   = symaddr<float>(g_z1);
    __nv_bfloat16* pTb  = symaddr<__nv_bfloat16>(g_pTb);
    __nv_bfloat16* wInT = symaddr<__nv_bfloat16>(g_wInT);
    __nv_bfloat16* wqT  = symaddr<__nv_bfloat16>(g_wqT);
    __nv_bfloat16* wkT  = symaddr<__nv_bfloat16>(g_wkT);
    __nv_bfloat16* wvT  = symaddr<__nv_bfloat16>(g_wvT);
    __nv_bfloat16* woT  = symaddr<__nv_bfloat16>(g_woT);
    __nv_bfloat16* w1T  = symaddr<__nv_bfloat16>(g_w1T);
    __nv_bfloat16* w2T  = symaddr<__nv_bfloat16>(g_w2T);

    static bool attr_set = false;
    if (!attr_set) {
        cudaFuncSetAttribute(tgemm_kernel, cudaFuncAttributeMaxDynamicSharedMemorySize, TG_SMEM_BYTES);
        cudaFuncSetAttribute(ctx_kernel, cudaFuncAttributeMaxDynamicSharedMemorySize, NN * 64 * 4);
        cudaFuncSetAttribute(attnout_kernel, cudaFuncAttributeMaxDynamicSharedMemorySize, (CSM * 64 + CSM) * 4);
        attr_set = true;
    }

    dim3 blk256(256);
    dim3 t256(DIM / 64, ROWS_TOT / 128);
    dim3 t1024(FFH / 64, ROWS_TOT / 128);
    dim3 tdd(MP / 64, RH / 128);
    const int ctx_smem = NN * 64 * 4;
    const int out_smem = (CSM * 64 + CSM) * 4;

    // ---- prep: bf16 conversions / transposes ----
    f2b_kernel<<<(int)((ROWS_TOT * (size_t)IN_DIM + 255) / 256), 256>>>(x, xb, (size_t)ROWS_TOT * IN_DIM);
    wtrans_kernel<<<dim3(DIM / 32, IN_DIM / 32), dim3(32, 8)>>>(w_in, wInT, IN_DIM, DIM);
    for (int l = 0; l < 2; l++) {
        wtrans_kernel<<<dim3(DIM / 32, DIM / 32), dim3(32, 8)>>>(wq + (size_t)l * DIM * DIM, wqT + (size_t)l * DIM * DIM, DIM, DIM);
        wtrans_kernel<<<dim3(DIM / 32, DIM / 32), dim3(32, 8)>>>(wk + (size_t)l * DIM * DIM, wkT + (size_t)l * DIM * DIM, DIM, DIM);
        wtrans_kernel<<<dim3(DIM / 32, DIM / 32), dim3(32, 8)>>>(wv + (size_t)l * DIM * DIM, wvT + (size_t)l * DIM * DIM, DIM, DIM);
        wtrans_kernel<<<dim3(DIM / 32, DIM / 32), dim3(32, 8)>>>(wo + (size_t)l * DIM * DIM, woT + (size_t)l * DIM * DIM, DIM, DIM);
        wtrans_kernel<<<dim3(FFH / 32, DIM / 32), dim3(32, 8)>>>(w1 + (size_t)l * DIM * FFH, w1T + (size_t)l * DIM * FFH, DIM, FFH);
        wtrans_kernel<<<dim3(DIM / 32, FFH / 32), dim3(32, 8)>>>(w2 + (size_t)l * FFH * DIM, w2T + (size_t)l * FFH * DIM, FFH, DIM);
    }

    // ---- h = x @ w_in + b_in ----
    tgemm_kernel<<<t256, blk256, TG_SMEM_BYTES>>>(xb, wInT, b_in, nullptr, h, nullptr,
                                                  ROWS_TOT, DIM, IN_DIM, 0);

    for (int l = 0; l < 2; l++) {
        // --- attention ---
        ln_bf16_kernel<<<ROWS_TOT, 256>>>(h, ln1_g + l * DIM, ln1_b + l * DIM, yb);
        tgemm_kernel<<<t256, blk256, TG_SMEM_BYTES>>>(yb, wqT + (size_t)l * DIM * DIM, nullptr, nullptr, q, qb, ROWS_TOT, DIM, DIM, 0);
        tgemm_kernel<<<t256, blk256, TG_SMEM_BYTES>>>(yb, wkT + (size_t)l * DIM * DIM, nullptr, nullptr, k, kb, ROWS_TOT, DIM, DIM, 0);
        tgemm_kernel<<<t256, blk256, TG_SMEM_BYTES>>>(yb, wvT + (size_t)l * DIM * DIM, nullptr, nullptr, v, nullptr, ROWS_TOT, DIM, DIM, 0);

        projb_kernel<<<(MP * 64 + 255) / 256, 256>>>(proj + (size_t)l * MF * DH, pTb);
        // dd = (q*NORM) @ projT : [RH,64] x [MP,64]^T
        tgemm_kernel<<<tdd, blk256, TG_SMEM_BYTES>>>(qb, pTb, nullptr, nullptr, qp, nullptr, RH, MP, 64, 0);
        tgemm_kernel<<<tdd, blk256, TG_SMEM_BYTES>>>(kb, pTb, nullptr, nullptr, kp, nullptr, RH, MP, 64, 0);

        qexp_kernel<<<RH / 8, 256>>>(q, qp);
        kmax_init_kernel<<<1, 1024>>>(kmx);
        kmax_kernel<<<RH / 8, 256>>>(kp, kmx);
        kexp_kernel<<<RH / 8, 256>>>(k, kp, kmx);
        ksum_kernel<<<BB * HEADS, 256>>>(kp, ksm);
        ctx_kernel<<<BB * HEADS, 256, ctx_smem>>>(kp, v, ctx);
        attnout_kernel<<<BB * HEADS, 256, out_smem>>>(qp, ctx, ksm, ob);

        tgemm_kernel<<<t256, blk256, TG_SMEM_BYTES>>>(ob, woT + (size_t)l * DIM * DIM, bo + l * DIM, h, h, nullptr, ROWS_TOT, DIM, DIM, 0);

        // --- FFN ---
        ln_bf16_kernel<<<ROWS_TOT, 256>>>(h, ln2_g + l * DIM, ln2_b + l * DIM, yb);
        tgemm_kernel<<<t1024, blk256, TG_SMEM_BYTES>>>(yb, w1T + (size_t)l * DIM * FFH, b1 + l * FFH, nullptr, nullptr, ffhb, ROWS_TOT, FFH, DIM, 1);
        tgemm_kernel<<<t256, blk256, TG_SMEM_BYTES>>>(ffhb, w2T + (size_t)l * FFH * DIM, b2 + l * DIM, h, h, nullptr, ROWS_TOT, DIM, FFH, 0);
    }

    pool_kernel<<<BB, 256>>>(h, pool);
    ln_f32_kernel<<<BB, 256>>>(pool, hln_g, hln_b, z);
    head1_kernel<<<BB, 128>>>(z, wh1, bh1, z1);
    head2_kernel<<<BB, 128>>>(z1, wh2, bh2, out);
}

// round 5
// speedup vs baseline: 6.7408x; 4.4357x over previous
#include <cuda_runtime.h>
#include <cuda_bf16.h>
#include <math.h>
#include <limits.h>
#include <stdint.h>

// ---------------- problem constants ----------------
#define BB 256
#define NN 300
#define IN_DIM 1280
#define DIM 256
#define HEADS 4
#define DH 64
#define MF 266            // NB_FEAT
#define MP 320            // padded feature dim (multiple of 64)
#define NP 320            // padded sequence dim per head
#define FFH 1024
#define ROWS_TOT (BB*NN)  // 76800
#define RH (ROWS_TOT*HEADS) // 307200
#define BH (BB*HEADS)       // 1024

#define LN_EPS 1e-5f
#define KEPS 1e-4f
#define RATIO 0.061314066f          // 266^-0.5
#define NORM 0.35355339059327373f   // 64^-0.25

// ---------------- scratch ----------------
__device__ float          g_h   [ROWS_TOT*DIM];
__device__ __nv_bfloat16  g_yb  [ROWS_TOT*DIM];
__device__ float          g_q   [ROWS_TOT*DIM];
__device__ float          g_k   [ROWS_TOT*DIM];
__device__ float          g_v   [ROWS_TOT*DIM];
__device__ __nv_bfloat16  g_qb  [ROWS_TOT*DIM];
__device__ __nv_bfloat16  g_kb  [ROWS_TOT*DIM];
__device__ __nv_bfloat16  g_ob  [ROWS_TOT*DIM];
__device__ __nv_bfloat16  g_ffhb[ROWS_TOT*FFH];
__device__ __nv_bfloat16  g_xb  [ROWS_TOT*IN_DIM];
__device__ float          g_ddq [(size_t)RH*MP];     // q dot-products (fp32)
__device__ float          g_ddk [(size_t)RH*MP];     // k dot-products (fp32)
__device__ __nv_bfloat16  g_qpB [(size_t)BH*NN*MP];  // qp de-interleaved bf16
__device__ __nv_bfloat16  g_kpT [(size_t)BH*MP*NP];  // kp transposed bf16
__device__ __nv_bfloat16  g_vT  [(size_t)BH*128*NP]; // vAug^T bf16 (row 64 = ones)
__device__ __nv_bfloat16  g_ctxT[(size_t)BH*128*MP]; // ctxAug^T bf16
__device__ float          g_outA[(size_t)BH*NN*128]; // attn numerator+denom fp32
__device__ int            g_kmax[BH];
__device__ float          g_pool[BB*DIM];
__device__ float          g_z   [BB*DIM];
__device__ float          g_z1  [BB*128];
__device__ __nv_bfloat16  g_pTb [MP*64];
// transposed bf16 weights
__device__ __nv_bfloat16  g_wInT[DIM*IN_DIM];
__device__ __nv_bfloat16  g_wqT [2][DIM*DIM];
__device__ __nv_bfloat16  g_wkT [2][DIM*DIM];
__device__ __nv_bfloat16  g_wvT [2][DIM*DIM];
__device__ __nv_bfloat16  g_woT [2][DIM*DIM];
__device__ __nv_bfloat16  g_w1T [2][FFH*DIM];
__device__ __nv_bfloat16  g_w2T [2][DIM*FFH];

// ---------------- helpers ----------------
__device__ __forceinline__ int f2o(float f) {
    int i = __float_as_int(f);
    return i >= 0 ? i : (i ^ 0x7FFFFFFF);
}
__device__ __forceinline__ float o2f(int i) {
    return __int_as_float(i >= 0 ? i : (i ^ 0x7FFFFFFF));
}
__device__ __forceinline__ float tanh_fast(float a) {
    float t = __expf(-2.0f * fabsf(a));
    float r = (1.0f - t) / (1.0f + t);
    return copysignf(r, a);
}
__device__ __forceinline__ float gelu_tanh(float x) {
    float x3 = x * x * x;
    return 0.5f * x * (1.0f + tanh_fast(0.7978845608028654f * (x + 0.044715f * x3)));
}
__device__ __forceinline__ float blockReduceSum256(float v) {
    __shared__ float sh[8];
    __syncthreads();
    int lane = threadIdx.x & 31, w = threadIdx.x >> 5;
    #pragma unroll
    for (int o = 16; o; o >>= 1) v += __shfl_xor_sync(0xFFFFFFFFu, v, o);
    if (lane == 0) sh[w] = v;
    __syncthreads();
    if (threadIdx.x == 0) {
        float s = 0.f;
        #pragma unroll
        for (int i = 0; i < 8; i++) s += sh[i];
        sh[0] = s;
    }
    __syncthreads();
    return sh[0];
}
__device__ __forceinline__ uint32_t smem_u32(const void* p) {
    uint32_t a;
    asm("{ .reg .u64 t; cvta.to.shared.u64 t, %1; cvt.u32.u64 %0, t; }" : "=r"(a) : "l"(p));
    return a;
}

#define SWZ(off) ((off) ^ (((off) >> 3) & 0x70))

__device__ __forceinline__ void ldmatrix4(uint32_t* r, uint32_t addr) {
    asm volatile("ldmatrix.sync.aligned.m8n8.x4.shared.b16 {%0,%1,%2,%3}, [%4];"
        : "=r"(r[0]), "=r"(r[1]), "=r"(r[2]), "=r"(r[3]) : "r"(addr));
}
__device__ __forceinline__ void mma16816(float* c, const uint32_t* a, uint32_t b0, uint32_t b1) {
    asm volatile(
        "mma.sync.aligned.m16n8k16.row.col.f32.bf16.bf16.f32 "
        "{%0,%1,%2,%3}, {%4,%5,%6,%7}, {%8,%9}, {%0,%1,%2,%3};"
        : "+f"(c[0]), "+f"(c[1]), "+f"(c[2]), "+f"(c[3])
        : "r"(a[0]), "r"(a[1]), "r"(a[2]), "r"(a[3]), "r"(b0), "r"(b1));
}

#define TG_SMEM_BYTES 49152

// ---------------- bf16 HMMA GEMM (generic) ----------------
// C = act(A[M,K] @ Bt[N,K]^T + bias) (+res). M%128==0, N%64==0, K%64==0.
__global__ void __launch_bounds__(256) tgemm_kernel(
    const __nv_bfloat16* __restrict__ A, const __nv_bfloat16* __restrict__ Bt,
    const float* __restrict__ bias, const float* __restrict__ res,
    float* __restrict__ Cf, __nv_bfloat16* __restrict__ Cb,
    int M, int N, int K, int act)
{
    extern __shared__ __nv_bfloat16 sm[];
    const uint32_t aBase = smem_u32(sm);
    const uint32_t bBase = aBase + 32768;
    char* smc = (char*)sm;

    const int tid = threadIdx.x;
    const int wid = tid >> 5, lane = tid & 31;
    const int wm = wid & 3, wn = wid >> 2;
    const int row0 = blockIdx.y * 128, col0 = blockIdx.x * 64;
    const int tileid = lane >> 3, rit = lane & 7;
    const int gid = lane >> 2, tig = lane & 3;

    float acc[2][4][4];
    #pragma unroll
    for (int mt = 0; mt < 2; mt++)
        #pragma unroll
        for (int j = 0; j < 4; j++)
            #pragma unroll
            for (int r = 0; r < 4; r++) acc[mt][j][r] = 0.f;

    const int nch = K >> 6;
    {
        #pragma unroll
        for (int i = 0; i < 4; i++) {
            int lin = tid + i * 256;
            int r = lin >> 3, c16 = lin & 7;
            uint4 d = *(const uint4*)(A + (size_t)(row0 + r) * K + c16 * 8);
            *(uint4*)(smc + SWZ(r * 128 + c16 * 16)) = d;
        }
        #pragma unroll
        for (int i = 0; i < 2; i++) {
            int lin = tid + i * 256;
            int r = lin >> 3, c16 = lin & 7;
            uint4 d = *(const uint4*)(Bt + (size_t)(col0 + r) * K + c16 * 8);
            *(uint4*)(smc + 32768 + SWZ(r * 128 + c16 * 16)) = d;
        }
    }
    __syncthreads();

    for (int c = 0; c < nch; c++) {
        const int buf = c & 1;
        const bool has_next = (c + 1) < nch;
        uint4 pa[4], pb[2];
        if (has_next) {
            const int k0 = (c + 1) << 6;
            #pragma unroll
            for (int i = 0; i < 4; i++) {
                int lin = tid + i * 256;
                int r = lin >> 3, c16 = lin & 7;
                pa[i] = *(const uint4*)(A + (size_t)(row0 + r) * K + k0 + c16 * 8);
            }
            #pragma unroll
            for (int i = 0; i < 2; i++) {
                int lin = tid + i * 256;
                int r = lin >> 3, c16 = lin & 7;
                pb[i] = *(const uint4*)(Bt + (size_t)(col0 + r) * K + k0 + c16 * 8);
            }
        }
        const uint32_t aB = aBase + buf * 16384;
        const uint32_t bB = bBase + buf * 8192;
        #pragma unroll
        for (int kk = 0; kk < 4; kk++) {
            uint32_t af[2][4];
            #pragma unroll
            for (int mt = 0; mt < 2; mt++) {
                int off = (wm * 32 + mt * 16 + (tileid & 1) * 8 + rit) * 128
                          + kk * 32 + (tileid >> 1) * 16;
                ldmatrix4(af[mt], aB + SWZ(off));
            }
            uint32_t bf[2][4];
            #pragma unroll
            for (int nt = 0; nt < 2; nt++) {
                int off = (wn * 32 + nt * 16 + (tileid & 1) * 8 + rit) * 128
                          + kk * 32 + (tileid >> 1) * 16;
                ldmatrix4(bf[nt], bB + SWZ(off));
            }
            #pragma unroll
            for (int mt = 0; mt < 2; mt++)
                #pragma unroll
                for (int j = 0; j < 4; j++) {
                    int nt = j >> 1, sel = j & 1;
                    mma16816(acc[mt][j], af[mt], bf[nt][sel], bf[nt][2 + sel]);
                }
        }
        if (has_next) {
            const int nb = buf ^ 1;
            #pragma unroll
            for (int i = 0; i < 4; i++) {
                int lin = tid + i * 256;
                int r = lin >> 3, c16 = lin & 7;
                *(uint4*)(smc + nb * 16384 + SWZ(r * 128 + c16 * 16)) = pa[i];
            }
            #pragma unroll
            for (int i = 0; i < 2; i++) {
                int lin = tid + i * 256;
                int r = lin >> 3, c16 = lin & 7;
                *(uint4*)(smc + 32768 + nb * 8192 + SWZ(r * 128 + c16 * 16)) = pb[i];
            }
        }
        __syncthreads();
    }

    #pragma unroll
    for (int mt = 0; mt < 2; mt++) {
        #pragma unroll
        for (int j = 0; j < 4; j++) {
            #pragma unroll
            for (int half = 0; half < 2; half++) {
                int r = row0 + wm * 32 + mt * 16 + gid + half * 8;
                int cidx = col0 + wn * 32 + j * 8 + tig * 2;
                float v0 = acc[mt][j][half * 2 + 0];
                float v1 = acc[mt][j][half * 2 + 1];
                if (bias) { v0 += bias[cidx]; v1 += bias[cidx + 1]; }
                if (act == 1) { v0 = gelu_tanh(v0); v1 = gelu_tanh(v1); }
                if (res) {
                    float2 r2 = *(const float2*)(res + (size_t)r * N + cidx);
                    v0 += r2.x; v1 += r2.y;
                }
                if (Cf) *(float2*)(Cf + (size_t)r * N + cidx) = make_float2(v0, v1);
                if (Cb) *(__nv_bfloat162*)(Cb + (size_t)r * N + cidx) = __floats2bfloat162_rn(v0, v1);
            }
        }
    }
}

// ---------------- batched bf16 HMMA GEMM ----------------
// Per batch z: C = A[.,K] @ Bt[.,K]^T.  A rows clamped to aClamp (for M padding),
// stores guarded by r < mValid. Row strides of A/Bt = K, C row stride = ldc.
__global__ void __launch_bounds__(256) btgemm_kernel(
    const __nv_bfloat16* __restrict__ A, size_t aBS, int aClamp,
    const __nv_bfloat16* __restrict__ Bt, size_t bBS,
    float* __restrict__ Cf, __nv_bfloat16* __restrict__ Cb, size_t cBS,
    int ldc, int K, int mValid)
{
    extern __shared__ __nv_bfloat16 sm[];
    const uint32_t aBase = smem_u32(sm);
    const uint32_t bBase = aBase + 32768;
    char* smc = (char*)sm;

    const int tid = threadIdx.x;
    const int wid = tid >> 5, lane = tid & 31;
    const int wm = wid & 3, wn = wid >> 2;
    const int row0 = blockIdx.y * 128, col0 = blockIdx.x * 64;
    const int tileid = lane >> 3, rit = lane & 7;
    const int gid = lane >> 2, tig = lane & 3;
    const int bh = blockIdx.z;

    const __nv_bfloat16* Ab = A + (size_t)bh * aBS;
    const __nv_bfloat16* Bb = Bt + (size_t)bh * bBS;

    float acc[2][4][4];
    #pragma unroll
    for (int mt = 0; mt < 2; mt++)
        #pragma unroll
        for (int j = 0; j < 4; j++)
            #pragma unroll
            for (int r = 0; r < 4; r++) acc[mt][j][r] = 0.f;

    const int nch = K >> 6;
    {
        #pragma unroll
        for (int i = 0; i < 4; i++) {
            int lin = tid + i * 256;
            int r = lin >> 3, c16 = lin & 7;
            int rg = min(row0 + r, aClamp);
            uint4 d = *(const uint4*)(Ab + (size_t)rg * K + c16 * 8);
            *(uint4*)(smc + SWZ(r * 128 + c16 * 16)) = d;
        }
        #pragma unroll
        for (int i = 0; i < 2; i++) {
            int lin = tid + i * 256;
            int r = lin >> 3, c16 = lin & 7;
            uint4 d = *(const uint4*)(Bb + (size_t)(col0 + r) * K + c16 * 8);
            *(uint4*)(smc + 32768 + SWZ(r * 128 + c16 * 16)) = d;
        }
    }
    __syncthreads();

    for (int c = 0; c < nch; c++) {
        const int buf = c & 1;
        const bool has_next = (c + 1) < nch;
        uint4 pa[4], pb[2];
        if (has_next) {
            const int k0 = (c + 1) << 6;
            #pragma unroll
            for (int i = 0; i < 4; i++) {
                int lin = tid + i * 256;
                int r = lin >> 3, c16 = lin & 7;
                int rg = min(row0 + r, aClamp);
                pa[i] = *(const uint4*)(Ab + (size_t)rg * K + k0 + c16 * 8);
            }
            #pragma unroll
            for (int i = 0; i < 2; i++) {
                int lin = tid + i * 256;
                int r = lin >> 3, c16 = lin & 7;
                pb[i] = *(const uint4*)(Bb + (size_t)(col0 + r) * K + k0 + c16 * 8);
            }
        }
        const uint32_t aB = aBase + buf * 16384;
        const uint32_t bB = bBase + buf * 8192;
        #pragma unroll
        for (int kk = 0; kk < 4; kk++) {
            uint32_t af[2][4];
            #pragma unroll
            for (int mt = 0; mt < 2; mt++) {
                int off = (wm * 32 + mt * 16 + (tileid & 1) * 8 + rit) * 128
                          + kk * 32 + (tileid >> 1) * 16;
                ldmatrix4(af[mt], aB + SWZ(off));
            }
            uint32_t bf[2][4];
            #pragma unroll
            for (int nt = 0; nt < 2; nt++) {
                int off = (wn * 32 + nt * 16 + (tileid & 1) * 8 + rit) * 128
                          + kk * 32 + (tileid >> 1) * 16;
                ldmatrix4(bf[nt], bB + SWZ(off));
            }
            #pragma unroll
            for (int mt = 0; mt < 2; mt++)
                #pragma unroll
                for (int j = 0; j < 4; j++) {
                    int nt = j >> 1, sel = j & 1;
                    mma16816(acc[mt][j], af[mt], bf[nt][sel], bf[nt][2 + sel]);
                }
        }
        if (has_next) {
            const int nb = buf ^ 1;
            #pragma unroll
            for (int i = 0; i < 4; i++) {
                int lin = tid + i * 256;
                int r = lin >> 3, c16 = lin & 7;
                *(uint4*)(smc + nb * 16384 + SWZ(r * 128 + c16 * 16)) = pa[i];
            }
            #pragma unroll
            for (int i = 0; i < 2; i++) {
                int lin = tid + i * 256;
                int r = lin >> 3, c16 = lin & 7;
                *(uint4*)(smc + 32768 + nb * 8192 + SWZ(r * 128 + c16 * 16)) = pb[i];
            }
        }
        __syncthreads();
    }

    float* Cfb = Cf ? Cf + (size_t)bh * cBS : nullptr;
    __nv_bfloat16* Cbb = Cb ? Cb + (size_t)bh * cBS : nullptr;
    #pragma unroll
    for (int mt = 0; mt < 2; mt++) {
        #pragma unroll
        for (int j = 0; j < 4; j++) {
            #pragma unroll
            for (int half = 0; half < 2; half++) {
                int r = row0 + wm * 32 + mt * 16 + gid + half * 8;
                if (r >= mValid) continue;
                int cidx = col0 + wn * 32 + j * 8 + tig * 2;
                float v0 = acc[mt][j][half * 2 + 0];
                float v1 = acc[mt][j][half * 2 + 1];
                if (Cfb) *(float2*)(Cfb + (size_t)r * ldc + cidx) = make_float2(v0, v1);
                if (Cbb) *(__nv_bfloat162*)(Cbb + (size_t)r * ldc + cidx) = __floats2bfloat162_rn(v0, v1);
            }
        }
    }
}

// ---------------- prep kernels ----------------
__global__ void f2b_kernel(const float* __restrict__ a, __nv_bfloat16* __restrict__ b, size_t n) {
    size_t i = (size_t)blockIdx.x * blockDim.x + threadIdx.x;
    if (i < n) b[i] = __float2bfloat16(a[i]);
}

__global__ void wtrans_kernel(const float* __restrict__ W, __nv_bfloat16* __restrict__ Wt,
                              int K, int N) {
    __shared__ float t[32][33];
    int k0 = blockIdx.y * 32, n0 = blockIdx.x * 32;
    int tx = threadIdx.x, ty = threadIdx.y;
    #pragma unroll
    for (int i = 0; i < 32; i += 8)
        t[ty + i][tx] = W[(size_t)(k0 + ty + i) * N + n0 + tx];
    __syncthreads();
    #pragma unroll
    for (int i = 0; i < 32; i += 8)
        Wt[(size_t)(n0 + ty + i) * K + k0 + tx] = __float2bfloat16(t[tx][ty + i]);
}

__global__ void projb_kernel(const float* __restrict__ proj, __nv_bfloat16* __restrict__ pTb) {
    int i = blockIdx.x * 256 + threadIdx.x;
    if (i >= MP * 64) return;
    int m = i >> 6, d = i & 63;
    pTb[i] = __float2bfloat16((m < MF) ? proj[m * 64 + d] * NORM : 0.f);
}

// ---------------- layernorm ----------------
__global__ void ln_bf16_kernel(const float* __restrict__ x, const float* __restrict__ g,
                               const float* __restrict__ b, __nv_bfloat16* __restrict__ y)
{
    int row = blockIdx.x;
    int t = threadIdx.x;
    float v = x[(size_t)row * DIM + t];
    float mu = blockReduceSum256(v) * (1.0f / DIM);
    float d = v - mu;
    float var = blockReduceSum256(d * d) * (1.0f / DIM);
    y[(size_t)row * DIM + t] = __float2bfloat16(d * rsqrtf(var + LN_EPS) * g[t] + b[t]);
}

__global__ void ln_f32_kernel(const float* __restrict__ x, const float* __restrict__ g,
                              const float* __restrict__ b, float* __restrict__ y)
{
    int row = blockIdx.x;
    int t = threadIdx.x;
    float v = x[(size_t)row * DIM + t];
    float mu = blockReduceSum256(v) * (1.0f / DIM);
    float d = v - mu;
    float var = blockReduceSum256(d * d) * (1.0f / DIM);
    y[(size_t)row * DIM + t] = d * rsqrtf(var + LN_EPS) * g[t] + b[t];
}

// ---------------- FAVOR+ passes ----------------
// dd rows: w = (b*NN+n)*HEADS+h, stride MP.
// qexp: per-row max stabilizer, writes de-interleaved bf16 qpB[bh][n][m] (m-padded).
__global__ void qexp_kernel(const float* __restrict__ q, const float* __restrict__ dd,
                            __nv_bfloat16* __restrict__ qpB)
{
    int w = (blockIdx.x * 256 + threadIdx.x) >> 5;
    int lane = threadIdx.x & 31;
    if (w >= RH) return;
    const float* qr = q + (size_t)w * 64;
    float a = qr[lane], b2 = qr[lane + 32];
    float s = a * a + b2 * b2;
    #pragma unroll
    for (int o = 16; o; o >>= 1) s += __shfl_xor_sync(0xFFFFFFFFu, s, o);
    float diag = 0.0625f * s;
    const float* row = dd + (size_t)w * MP;
    float vv[9], mx = -1e30f;
    #pragma unroll
    for (int i = 0; i < 9; i++) {
        int m = lane + 32 * i;
        vv[i] = (m < MF) ? row[m] : -1e30f;
        mx = fmaxf(mx, vv[i]);
    }
    #pragma unroll
    for (int o = 16; o; o >>= 1) mx = fmaxf(mx, __shfl_xor_sync(0xFFFFFFFFu, mx, o));

    int b = w / (NN * HEADS);
    int rem = w - b * NN * HEADS;
    int n = rem >> 2, h = rem & 3;
    __nv_bfloat16* orow = qpB + ((size_t)(b * HEADS + h) * NN + n) * MP;
    #pragma unroll
    for (int i = 0; i < 9; i++) {
        int m = lane + 32 * i;
        if (m < MF) orow[m] = __float2bfloat16(RATIO * (__expf(vv[i] - diag - mx) + KEPS));
        else orow[m] = __float2bfloat16(0.f);
    }
    int m9 = lane + 288;
    orow[m9] = __float2bfloat16(0.f);
}

__global__ void kmax_init_kernel(int* __restrict__ kmax) {
    int i = blockIdx.x * blockDim.x + threadIdx.x;
    if (i < BH) kmax[i] = INT_MIN;
}

__global__ void kmax_kernel(const float* __restrict__ dd, int* __restrict__ kmax)
{
    int w = (blockIdx.x * 256 + threadIdx.x) >> 5;
    int lane = threadIdx.x & 31;
    if (w >= RH) return;
    const float* row = dd + (size_t)w * MP;
    float mx = -1e30f;
    #pragma unroll
    for (int i = 0; i < 9; i++) {
        int m = lane + 32 * i;
        if (m < MF) mx = fmaxf(mx, row[m]);
    }
    #pragma unroll
    for (int o = 16; o; o >>= 1) mx = fmaxf(mx, __shfl_xor_sync(0xFFFFFFFFu, mx, o));
    if (lane == 0) {
        int bh = (w / (NN * HEADS)) * HEADS + (w & 3);
        atomicMax(&kmax[bh], f2o(mx));
    }
}

// kexp + transpose: writes kpT[bh][m][n] bf16, zero-padded in both dims.
__global__ void __launch_bounds__(256) kexpT_kernel(
    const float* __restrict__ k, const float* __restrict__ dd,
    const int* __restrict__ kmax, __nv_bfloat16* __restrict__ kpT)
{
    __shared__ float s[32][325];
    __shared__ float diag[32];
    int bh = blockIdx.x, b = bh >> 2, h = bh & 3;
    int n0 = blockIdx.y * 32;
    int tid = threadIdx.x;
    int wid = tid >> 5, lane = tid & 31;

    // diag per n (warp wid handles n_l = wid*4 .. +3)
    #pragma unroll
    for (int ii = 0; ii < 4; ii++) {
        int n_l = wid * 4 + ii;
        int n_g = n0 + n_l;
        float sum = 0.f;
        if (n_g < NN) {
            const float* kr = k + ((size_t)(b * NN + n_g)) * DIM + h * 64;
            float a = kr[lane], b2 = kr[lane + 32];
            sum = a * a + b2 * b2;
        }
        #pragma unroll
        for (int o = 16; o; o >>= 1) sum += __shfl_xor_sync(0xFFFFFFFFu, sum, o);
        if (lane == 0) diag[n_l] = 0.0625f * sum;
    }

    // load dd tile [32 n][320 m]
    #pragma unroll
    for (int it = 0; it < 4; it++) {
        int n_l = (tid >> 5) + 8 * it;
        int n_g = n0 + n_l;
        const float* row = dd + ((size_t)((b * NN + min(n_g, NN - 1)) * HEADS) + h) * MP;
        bool ok = n_g < NN;
        #pragma unroll
        for (int j = 0; j < 10; j++) {
            int m = lane + 32 * j;
            s[n_l][m] = ok ? row[m] : 0.f;
        }
    }
    __syncthreads();

    float stab = o2f(kmax[bh]);
    int n_g = n0 + lane;
    bool nok = n_g < NN;
    float dg = diag[lane];
    __nv_bfloat16* base = kpT + (size_t)bh * MP * NP + n0 + lane;
    for (int m = wid; m < MP; m += 8) {
        float val = 0.f;
        if (m < MF && nok)
            val = RATIO * (__expf(s[lane][m] - dg - stab) + KEPS);
        base[(size_t)m * NP] = __float2bfloat16(val);
    }
}

// v transpose: vAugT[bh][d][n], d=0..63 = v^T, d=64 = ones, d=65..127 = 0.
__global__ void __launch_bounds__(256) vtrans_kernel(
    const float* __restrict__ v, __nv_bfloat16* __restrict__ vT)
{
    __shared__ float t[32][65];
    int bh = blockIdx.x, b = bh >> 2, h = bh & 3;
    int tid = threadIdx.x;
    int lane = tid & 31;
    __nv_bfloat16* vb = vT + (size_t)bh * 128 * NP;

    for (int it = 0; it < 10; it++) {
        int n0 = it * 32;
        int d = tid & 63;
        #pragma unroll
        for (int sub = 0; sub < 8; sub++) {
            int n_l = (tid >> 6) + 4 * sub;
            int n_g = n0 + n_l;
            t[n_l][d] = (n_g < NN) ? v[((size_t)(b * NN + n_g)) * DIM + h * 64 + d] : 0.f;
        }
        __syncthreads();
        int dcol = tid >> 5;
        #pragma unroll
        for (int j = 0; j < 8; j++) {
            int d2 = dcol + 8 * j;
            vb[(size_t)d2 * NP + n0 + lane] = __float2bfloat16(t[lane][d2]);
        }
        __syncthreads();
    }
    // rows 64..127
    for (int idx = tid; idx < 64 * NP; idx += 256) {
        int d = 64 + idx / NP, n = idx % NP;
        float val = (d == 64 && n < NN) ? 1.f : 0.f;
        vb[(size_t)d * NP + n] = __float2bfloat16(val);
    }
}

// divide: ob = numerator / denominator, re-interleaved bf16
__global__ void divout_kernel(const float* __restrict__ outA, __nv_bfloat16* __restrict__ ob)
{
    int bh = blockIdx.x, b = bh >> 2, h = bh & 3;
    const float* base = outA + (size_t)bh * NN * 128;
    for (int idx = threadIdx.x; idx < NN * 64; idx += 256) {
        int n = idx >> 6, d = idx & 63;
        float num = base[(size_t)n * 128 + d];
        float den = base[(size_t)n * 128 + 64];
        ob[((size_t)(b * NN + n)) * DIM + h * 64 + d] = __float2bfloat16(num / den);
    }
}

// ---------------- pooling & head ----------------
__global__ void pool_kernel(const float* __restrict__ h, float* __restrict__ pooled)
{
    int b = blockIdx.x, c = threadIdx.x;
    const float* p = h + (size_t)b * NN * DIM + c;
    float s0 = 0.f, s1 = 0.f, s2 = 0.f, s3 = 0.f;
    for (int n = 0; n < NN; n += 4) {
        s0 += p[(size_t)(n + 0) * DIM];
        s1 += p[(size_t)(n + 1) * DIM];
        s2 += p[(size_t)(n + 2) * DIM];
        s3 += p[(size_t)(n + 3) * DIM];
    }
    pooled[b * DIM + c] = ((s0 + s1) + (s2 + s3)) * (1.0f / NN);
}

__global__ void head1_kernel(const float* __restrict__ z, const float* __restrict__ w,
                             const float* __restrict__ bias, float* __restrict__ z1)
{
    __shared__ float zs[DIM];
    int b = blockIdx.x, j = threadIdx.x;
    for (int c = j; c < DIM; c += 128) zs[c] = z[b * DIM + c];
    __syncthreads();
    float s0 = 0.f, s1 = 0.f, s2 = 0.f, s3 = 0.f;
    #pragma unroll 1
    for (int c = 0; c < DIM; c += 4) {
        s0 = fmaf(zs[c + 0], w[(c + 0) * 128 + j], s0);
        s1 = fmaf(zs[c + 1], w[(c + 1) * 128 + j], s1);
        s2 = fmaf(zs[c + 2], w[(c + 2) * 128 + j], s2);
        s3 = fmaf(zs[c + 3], w[(c + 3) * 128 + j], s3);
    }
    z1[b * 128 + j] = fmaxf(((s0 + s1) + (s2 + s3)) + bias[j], 0.f);
}

__global__ void head2_kernel(const float* __restrict__ z1, const float* __restrict__ w,
                             const float* __restrict__ bias, float* __restrict__ out)
{
    __shared__ float sh[4];
    int b = blockIdx.x, j = threadIdx.x;
    float s = z1[b * 128 + j] * w[j];
    #pragma unroll
    for (int o = 16; o; o >>= 1) s += __shfl_xor_sync(0xFFFFFFFFu, s, o);
    if ((j & 31) == 0) sh[j >> 5] = s;
    __syncthreads();
    if (j == 0) {
        float t = sh[0] + sh[1] + sh[2] + sh[3] + bias[0];
        out[b] = 1.0f / (1.0f + __expf(-t));
    }
}

// ---------------- host ----------------
template <typename T> static T* symaddr(const void* sym) {
    void* p = nullptr;
    cudaGetSymbolAddress(&p, sym);
    return (T*)p;
}

extern "C" void kernel_launch(void* const* d_in, const int* in_sizes, int n_in,
                              void* d_out, int out_size)
{
    const float* x     = (const float*)d_in[0];
    const float* w_in  = (const float*)d_in[1];
    const float* b_in  = (const float*)d_in[2];
    const float* proj  = (const float*)d_in[3];
    const float* ln1_g = (const float*)d_in[4];
    const float* ln1_b = (const float*)d_in[5];
    const float* wq    = (const float*)d_in[6];
    const float* wk    = (const float*)d_in[7];
    const float* wv    = (const float*)d_in[8];
    const float* wo    = (const float*)d_in[9];
    const float* bo    = (const float*)d_in[10];
    const float* ln2_g = (const float*)d_in[11];
    const float* ln2_b = (const float*)d_in[12];
    const float* w1    = (const float*)d_in[13];
    const float* b1    = (const float*)d_in[14];
    const float* w2    = (const float*)d_in[15];
    const float* b2    = (const float*)d_in[16];
    const float* hln_g = (const float*)d_in[17];
    const float* hln_b = (const float*)d_in[18];
    const float* wh1   = (const float*)d_in[19];
    const float* bh1   = (const float*)d_in[20];
    const float* wh2   = (const float*)d_in[21];
    const float* bh2   = (const float*)d_in[22];
    float* out = (float*)d_out;

    float* h    = symaddr<float>(g_h);
    __nv_bfloat16* yb   = symaddr<__nv_bfloat16>(g_yb);
    float* q    = symaddr<float>(g_q);
    float* k    = symaddr<float>(g_k);
    float* v    = symaddr<float>(g_v);
    __nv_bfloat16* qb   = symaddr<__nv_bfloat16>(g_qb);
    __nv_bfloat16* kb   = symaddr<__nv_bfloat16>(g_kb);
    __nv_bfloat16* ob   = symaddr<__nv_bfloat16>(g_ob);
    __nv_bfloat16* ffhb = symaddr<__nv_bfloat16>(g_ffhb);
    __nv_bfloat16* xb   = symaddr<__nv_bfloat16>(g_xb);
    float* ddq  = symaddr<float>(g_ddq);
    float* ddk  = symaddr<float>(g_ddk);
    __nv_bfloat16* qpB  = symaddr<__nv_bfloat16>(g_qpB);
    __nv_bfloat16* kpT  = symaddr<__nv_bfloat16>(g_kpT);
    __nv_bfloat16* vT   = symaddr<__nv_bfloat16>(g_vT);
    __nv_bfloat16* ctxT = symaddr<__nv_bfloat16>(g_ctxT);
    float* outA = symaddr<float>(g_outA);
    int*   kmx  = symaddr<int>(g_kmax);
    float* pool = symaddr<float>(g_pool);
    float* z    = symaddr<float>(g_z);
    float* z1   = symaddr<float>(g_z1);
    __nv_bfloat16* pTb  = symaddr<__nv_bfloat16>(g_pTb);
    __nv_bfloat16* wInT = symaddr<__nv_bfloat16>(g_wInT);
    __nv_bfloat16* wqT  = symaddr<__nv_bfloat16>(g_wqT);
    __nv_bfloat16* wkT  = symaddr<__nv_bfloat16>(g_wkT);
    __nv_bfloat16* wvT  = symaddr<__nv_bfloat16>(g_wvT);
    __nv_bfloat16* woT  = symaddr<__nv_bfloat16>(g_woT);
    __nv_bfloat16* w1T  = symaddr<__nv_bfloat16>(g_w1T);
    __nv_bfloat16* w2T  = symaddr<__nv_bfloat16>(g_w2T);

    static bool attr_set = false;
    if (!attr_set) {
        cudaFuncSetAttribute(tgemm_kernel, cudaFuncAttributeMaxDynamicSharedMemorySize, TG_SMEM_BYTES);
        cudaFuncSetAttribute(btgemm_kernel, cudaFuncAttributeMaxDynamicSharedMemorySize, TG_SMEM_BYTES);
        attr_set = true;
    }

    dim3 blk256(256);
    dim3 t256(DIM / 64, ROWS_TOT / 128);
    dim3 t1024(FFH / 64, ROWS_TOT / 128);
    dim3 tdd(MP / 64, RH / 128);
    dim3 gCtx(MP / 64, 1, BH);          // ctxT: N=MP tiles, M=128
    dim3 gAtt(2, 3, BH);                // attnout: N=128 (2 tiles), M=300 (3 tiles)

    // ---- prep ----
    f2b_kernel<<<(int)((ROWS_TOT * (size_t)IN_DIM + 255) / 256), 256>>>(x, xb, (size_t)ROWS_TOT * IN_DIM);
    wtrans_kernel<<<dim3(DIM / 32, IN_DIM / 32), dim3(32, 8)>>>(w_in, wInT, IN_DIM, DIM);
    for (int l = 0; l < 2; l++) {
        wtrans_kernel<<<dim3(DIM / 32, DIM / 32), dim3(32, 8)>>>(wq + (size_t)l * DIM * DIM, wqT + (size_t)l * DIM * DIM, DIM, DIM);
        wtrans_kernel<<<dim3(DIM / 32, DIM / 32), dim3(32, 8)>>>(wk + (size_t)l * DIM * DIM, wkT + (size_t)l * DIM * DIM, DIM, DIM);
        wtrans_kernel<<<dim3(DIM / 32, DIM / 32), dim3(32, 8)>>>(wv + (size_t)l * DIM * DIM, wvT + (size_t)l * DIM * DIM, DIM, DIM);
        wtrans_kernel<<<dim3(DIM / 32, DIM / 32), dim3(32, 8)>>>(wo + (size_t)l * DIM * DIM, woT + (size_t)l * DIM * DIM, DIM, DIM);
        wtrans_kernel<<<dim3(FFH / 32, DIM / 32), dim3(32, 8)>>>(w1 + (size_t)l * DIM * FFH, w1T + (size_t)l * DIM * FFH, DIM, FFH);
        wtrans_kernel<<<dim3(DIM / 32, FFH / 32), dim3(32, 8)>>>(w2 + (size_t)l * FFH * DIM, w2T + (size_t)l * FFH * DIM, FFH, DIM);
    }

    // ---- h = x @ w_in + b_in ----
    tgemm_kernel<<<t256, blk256, TG_SMEM_BYTES>>>(xb, wInT, b_in, nullptr, h, nullptr,
                                                  ROWS_TOT, DIM, IN_DIM, 0);

    for (int l = 0; l < 2; l++) {
        // --- attention ---
        ln_bf16_kernel<<<ROWS_TOT, 256>>>(h, ln1_g + l * DIM, ln1_b + l * DIM, yb);
        tgemm_kernel<<<t256, blk256, TG_SMEM_BYTES>>>(yb, wqT + (size_t)l * DIM * DIM, nullptr, nullptr, q, qb, ROWS_TOT, DIM, DIM, 0);
        tgemm_kernel<<<t256, blk256, TG_SMEM_BYTES>>>(yb, wkT + (size_t)l * DIM * DIM, nullptr, nullptr, k, kb, ROWS_TOT, DIM, DIM, 0);
        tgemm_kernel<<<t256, blk256, TG_SMEM_BYTES>>>(yb, wvT + (size_t)l * DIM * DIM, nullptr, nullptr, v, nullptr, ROWS_TOT, DIM, DIM, 0);

        projb_kernel<<<(MP * 64 + 255) / 256, 256>>>(proj + (size_t)l * MF * DH, pTb);
        tgemm_kernel<<<tdd, blk256, TG_SMEM_BYTES>>>(qb, pTb, nullptr, nullptr, ddq, nullptr, RH, MP, 64, 0);
        tgemm_kernel<<<tdd, blk256, TG_SMEM_BYTES>>>(kb, pTb, nullptr, nullptr, ddk, nullptr, RH, MP, 64, 0);

        qexp_kernel<<<RH / 8, 256>>>(q, ddq, qpB);
        kmax_init_kernel<<<1, 1024>>>(kmx);
        kmax_kernel<<<RH / 8, 256>>>(ddk, kmx);
        kexpT_kernel<<<dim3(BH, 10), 256>>>(k, ddk, kmx, kpT);
        vtrans_kernel<<<BH, 256>>>(v, vT);

        // ctxT[bh] = vAugT[128 x 320n] @ kpT[320m x 320n]^T  -> [128 x 320m] bf16
        btgemm_kernel<<<gCtx, blk256, TG_SMEM_BYTES>>>(
            vT, (size_t)128 * NP, 127, kpT, (size_t)MP * NP,
            nullptr, ctxT, (size_t)128 * MP, MP, NP, 128);
        // outA[bh] = qpB[300 x 320m] @ ctxT[128 x 320m]^T -> [300 x 128] fp32
        btgemm_kernel<<<gAtt, blk256, TG_SMEM_BYTES>>>(
            qpB, (size_t)NN * MP, NN - 1, ctxT, (size_t)128 * MP,
            outA, nullptr, (size_t)NN * 128, 128, MP, NN);

        divout_kernel<<<BH, 256>>>(outA, ob);

        tgemm_kernel<<<t256, blk256, TG_SMEM_BYTES>>>(ob, woT + (size_t)l * DIM * DIM, bo + l * DIM, h, h, nullptr, ROWS_TOT, DIM, DIM, 0);

        // --- FFN ---
        ln_bf16_kernel<<<ROWS_TOT, 256>>>(h, ln2_g + l * DIM, ln2_b + l * DIM, yb);
        tgemm_kernel<<<t1024, blk256, TG_SMEM_BYTES>>>(yb, w1T + (size_t)l * DIM * FFH, b1 + l * FFH, nullptr, nullptr, ffhb, ROWS_TOT, FFH, DIM, 1);
        tgemm_kernel<<<t256, blk256, TG_SMEM_BYTES>>>(ffhb, w2T + (size_t)l * FFH * DIM, b2 + l * DIM, h, h, nullptr, ROWS_TOT, DIM, FFH, 0);
    }

    pool_kernel<<<BB, 256>>>(h, pool);
    ln_f32_kernel<<<BB, 256>>>(pool, hln_g, hln_b, z);
    head1_kernel<<<BB, 128>>>(z, wh1, bh1, z1);
    head2_kernel<<<BB, 128>>>(z1, wh2, bh2, out);
}

// round 6
// speedup vs baseline: 8.0025x; 1.1872x over previous
#include <cuda_runtime.h>
#include <cuda_bf16.h>
#include <math.h>
#include <limits.h>
#include <stdint.h>

// ---------------- problem constants ----------------
#define BB 256
#define NN 300
#define IN_DIM 1280
#define DIM 256
#define HEADS 4
#define DH 64
#define MF 266            // NB_FEAT
#define MP 320            // padded feature dim
#define NP 320            // padded sequence dim per head
#define FFH 1024
#define ROWS_TOT (BB*NN)  // 76800
#define RH (ROWS_TOT*HEADS) // 307200
#define BH (BB*HEADS)       // 1024
#define RPB (NN*HEADS)      // rows per batch in dd view = 1200

#define LN_EPS 1e-5f
#define KEPS 1e-4f
#define RATIO 0.061314066f
#define NORM 0.35355339059327373f

// ---------------- scratch ----------------
__device__ float          g_h   [ROWS_TOT*DIM];
__device__ __nv_bfloat16  g_yb  [ROWS_TOT*DIM];
__device__ __nv_bfloat16  g_qb  [ROWS_TOT*DIM];
__device__ __nv_bfloat16  g_kb  [ROWS_TOT*DIM];
__device__ __nv_bfloat16  g_vb  [ROWS_TOT*DIM];
__device__ __nv_bfloat16  g_ob  [ROWS_TOT*DIM];
__device__ __nv_bfloat16  g_ffhb[ROWS_TOT*FFH];
__device__ __nv_bfloat16  g_xb  [ROWS_TOT*IN_DIM];
__device__ float          g_ddq [(size_t)RH*MP];
__device__ float          g_ddk [(size_t)RH*MP];
__device__ __nv_bfloat16  g_qpB [(size_t)BH*NN*MP];
__device__ __nv_bfloat16  g_kpT [(size_t)BH*MP*NP];
__device__ __nv_bfloat16  g_vT  [(size_t)BH*128*NP];
__device__ __nv_bfloat16  g_ctxT[(size_t)BH*128*MP];
__device__ float          g_outA[(size_t)BH*NN*128];
__device__ int            g_kmax[BH];
__device__ float          g_pool[BB*DIM];
__device__ float          g_z   [BB*DIM];
__device__ float          g_z1  [BB*128];
__device__ __nv_bfloat16  g_pTb [MP*64];
__device__ __nv_bfloat16  g_wInT[DIM*IN_DIM];
__device__ __nv_bfloat16  g_wqT [2][DIM*DIM];
__device__ __nv_bfloat16  g_wkT [2][DIM*DIM];
__device__ __nv_bfloat16  g_wvT [2][DIM*DIM];
__device__ __nv_bfloat16  g_woT [2][DIM*DIM];
__device__ __nv_bfloat16  g_w1T [2][FFH*DIM];
__device__ __nv_bfloat16  g_w2T [2][DIM*FFH];

// ---------------- helpers ----------------
__device__ __forceinline__ int f2o(float f) {
    int i = __float_as_int(f);
    return i >= 0 ? i : (i ^ 0x7FFFFFFF);
}
__device__ __forceinline__ float o2f(int i) {
    return __int_as_float(i >= 0 ? i : (i ^ 0x7FFFFFFF));
}
__device__ __forceinline__ float tanh_fast(float a) {
    float t = __expf(-2.0f * fabsf(a));
    float r = (1.0f - t) / (1.0f + t);
    return copysignf(r, a);
}
__device__ __forceinline__ float gelu_tanh(float x) {
    float x3 = x * x * x;
    return 0.5f * x * (1.0f + tanh_fast(0.7978845608028654f * (x + 0.044715f * x3)));
}
__device__ __forceinline__ float blockReduceSum256(float v) {
    __shared__ float sh[8];
    __syncthreads();
    int lane = threadIdx.x & 31, w = threadIdx.x >> 5;
    #pragma unroll
    for (int o = 16; o; o >>= 1) v += __shfl_xor_sync(0xFFFFFFFFu, v, o);
    if (lane == 0) sh[w] = v;
    __syncthreads();
    if (threadIdx.x == 0) {
        float s = 0.f;
        #pragma unroll
        for (int i = 0; i < 8; i++) s += sh[i];
        sh[0] = s;
    }
    __syncthreads();
    return sh[0];
}
__device__ __forceinline__ uint32_t smem_u32(const void* p) {
    uint32_t a;
    asm("{ .reg .u64 t; cvta.to.shared.u64 t, %1; cvt.u32.u64 %0, t; }" : "=r"(a) : "l"(p));
    return a;
}

#define SWZ(off) ((off) ^ (((off) >> 3) & 0x70))

__device__ __forceinline__ void ldmatrix4(uint32_t* r, uint32_t addr) {
    asm volatile("ldmatrix.sync.aligned.m8n8.x4.shared.b16 {%0,%1,%2,%3}, [%4];"
        : "=r"(r[0]), "=r"(r[1]), "=r"(r[2]), "=r"(r[3]) : "r"(addr));
}
__device__ __forceinline__ void mma16816(float* c, const uint32_t* a, uint32_t b0, uint32_t b1) {
    asm volatile(
        "mma.sync.aligned.m16n8k16.row.col.f32.bf16.bf16.f32 "
        "{%0,%1,%2,%3}, {%4,%5,%6,%7}, {%8,%9}, {%0,%1,%2,%3};"
        : "+f"(c[0]), "+f"(c[1]), "+f"(c[2]), "+f"(c[3])
        : "r"(a[0]), "r"(a[1]), "r"(a[2]), "r"(a[3]), "r"(b0), "r"(b1));
}
__device__ __forceinline__ void cp_async16(uint32_t smem, const void* g) {
    asm volatile("cp.async.cg.shared.global [%0], [%1], 16;" :: "r"(smem), "l"(g));
}
__device__ __forceinline__ void cp_commit() {
    asm volatile("cp.async.commit_group;" ::: "memory");
}
__device__ __forceinline__ void cp_wait2() {
    asm volatile("cp.async.wait_group 2;" ::: "memory");
}

// stage stride: A 16384 + B 8192 = 24576; 3 stages = 73728
#define TG_STAGE 24576
#define TG_SMEM_BYTES (3*TG_STAGE)

// ---------------- bf16 HMMA GEMM (pipelined) ----------------
// C = act(A[M,K] @ Bt[N,K]^T + bias) (+res). M%128==0, N%64==0, K%64==0.
// kmaxOut: optional per-(b,h) ordered-int max of outputs with col<MF (dd-k fusion).
__global__ void __launch_bounds__(256) tgemm_kernel(
    const __nv_bfloat16* __restrict__ A, const __nv_bfloat16* __restrict__ Bt,
    const float* __restrict__ bias, const float* __restrict__ res,
    float* __restrict__ Cf, __nv_bfloat16* __restrict__ Cb,
    int M, int N, int K, int act, int* __restrict__ kmaxOut)
{
    extern __shared__ __nv_bfloat16 sm[];
    const uint32_t base = smem_u32(sm);
    __shared__ int smax[8];

    const int tid = threadIdx.x;
    const int wid = tid >> 5, lane = tid & 31;
    const int wm = wid & 3, wn = wid >> 2;
    const int row0 = blockIdx.y * 128, col0 = blockIdx.x * 64;
    const int tileid = lane >> 3, rit = lane & 7;
    const int gid = lane >> 2, tig = lane & 3;

    if (kmaxOut && tid < 8) smax[tid] = INT_MIN;

    float acc[2][4][4];
    #pragma unroll
    for (int mt = 0; mt < 2; mt++)
        #pragma unroll
        for (int j = 0; j < 4; j++)
            #pragma unroll
            for (int r = 0; r < 4; r++) acc[mt][j][r] = 0.f;

    const int nch = K >> 6;
    const __nv_bfloat16* Arow = A + (size_t)row0 * K;
    const __nv_bfloat16* Brow = Bt + (size_t)col0 * K;

    // preload 3 stages
    #pragma unroll
    for (int s = 0; s < 3; s++) {
        if (s < nch) {
            const int k0 = s << 6;
            const uint32_t aS = base + s * TG_STAGE;
            const uint32_t bS = aS + 16384;
            #pragma unroll
            for (int i = 0; i < 4; i++) {
                int lin = tid + i * 256;
                int r = lin >> 3, c8 = lin & 7;
                cp_async16(aS + SWZ(r * 128 + c8 * 16), Arow + (size_t)r * K + k0 + c8 * 8);
            }
            #pragma unroll
            for (int i = 0; i < 2; i++) {
                int lin = tid + i * 256;
                int r = lin >> 3, c8 = lin & 7;
                cp_async16(bS + SWZ(r * 128 + c8 * 16), Brow + (size_t)r * K + k0 + c8 * 8);
            }
        }
        cp_commit();
    }

    int stg = 0;
    for (int c = 0; c < nch; c++) {
        cp_wait2();
        __syncthreads();
        const uint32_t aB = base + stg * TG_STAGE;
        const uint32_t bB = aB + 16384;
        #pragma unroll
        for (int kk = 0; kk < 4; kk++) {
            uint32_t af[2][4];
            #pragma unroll
            for (int mt = 0; mt < 2; mt++) {
                int off = (wm * 32 + mt * 16 + (tileid & 1) * 8 + rit) * 128
                          + kk * 32 + (tileid >> 1) * 16;
                ldmatrix4(af[mt], aB + SWZ(off));
            }
            uint32_t bf[2][4];
            #pragma unroll
            for (int nt = 0; nt < 2; nt++) {
                int off = (wn * 32 + nt * 16 + (tileid & 1) * 8 + rit) * 128
                          + kk * 32 + (tileid >> 1) * 16;
                ldmatrix4(bf[nt], bB + SWZ(off));
            }
            #pragma unroll
            for (int mt = 0; mt < 2; mt++)
                #pragma unroll
                for (int j = 0; j < 4; j++) {
                    int nt = j >> 1, sel = j & 1;
                    mma16816(acc[mt][j], af[mt], bf[nt][sel], bf[nt][2 + sel]);
                }
        }
        __syncthreads();
        if (c + 3 < nch) {
            const int k0 = (c + 3) << 6;
            const uint32_t aS = base + stg * TG_STAGE;
            const uint32_t bS = aS + 16384;
            #pragma unroll
            for (int i = 0; i < 4; i++) {
                int lin = tid + i * 256;
                int r = lin >> 3, c8 = lin & 7;
                cp_async16(aS + SWZ(r * 128 + c8 * 16), Arow + (size_t)r * K + k0 + c8 * 8);
            }
            #pragma unroll
            for (int i = 0; i < 2; i++) {
                int lin = tid + i * 256;
                int r = lin >> 3, c8 = lin & 7;
                cp_async16(bS + SWZ(r * 128 + c8 * 16), Brow + (size_t)r * K + k0 + c8 * 8);
            }
        }
        cp_commit();
        stg = (stg + 1) == 3 ? 0 : stg + 1;
    }

    // epilogue
    float kmv[2] = {-1e30f, -1e30f};
    const int b0 = row0 / RPB;
    #pragma unroll
    for (int mt = 0; mt < 2; mt++) {
        #pragma unroll
        for (int j = 0; j < 4; j++) {
            #pragma unroll
            for (int half = 0; half < 2; half++) {
                int r = row0 + wm * 32 + mt * 16 + gid + half * 8;
                int cidx = col0 + wn * 32 + j * 8 + tig * 2;
                float v0 = acc[mt][j][half * 2 + 0];
                float v1 = acc[mt][j][half * 2 + 1];
                if (kmaxOut) {
                    int bs = (r / RPB == b0) ? 0 : 1;
                    float m = -1e30f;
                    if (cidx < MF) m = v0;
                    if (cidx + 1 < MF) m = fmaxf(m, v1);
                    kmv[bs] = fmaxf(kmv[bs], m);
                }
                if (bias) { v0 += bias[cidx]; v1 += bias[cidx + 1]; }
                if (act == 1) { v0 = gelu_tanh(v0); v1 = gelu_tanh(v1); }
                if (res) {
                    float2 r2 = *(const float2*)(res + (size_t)r * N + cidx);
                    v0 += r2.x; v1 += r2.y;
                }
                if (Cf) *(float2*)(Cf + (size_t)r * N + cidx) = make_float2(v0, v1);
                if (Cb) *(__nv_bfloat162*)(Cb + (size_t)r * N + cidx) = __floats2bfloat162_rn(v0, v1);
            }
        }
    }
    if (kmaxOut) {
        int h = (row0 + wm * 32 + gid) & 3;
        if (kmv[0] > -1e29f) atomicMax(&smax[h], f2o(kmv[0]));
        if (kmv[1] > -1e29f) atomicMax(&smax[4 + h], f2o(kmv[1]));
        __syncthreads();
        if (tid < 8) {
            int bsel = tid >> 2, hh = tid & 3;
            int bb = b0 + bsel;
            if (smax[tid] != INT_MIN && bb < BB)
                atomicMax(&kmaxOut[bb * HEADS + hh], smax[tid]);
        }
    }
}

// ---------------- batched bf16 HMMA GEMM (pipelined) ----------------
__global__ void __launch_bounds__(256) btgemm_kernel(
    const __nv_bfloat16* __restrict__ A, size_t aBS, int aClamp,
    const __nv_bfloat16* __restrict__ Bt, size_t bBS,
    float* __restrict__ Cf, __nv_bfloat16* __restrict__ Cb, size_t cBS,
    int ldc, int K, int mValid)
{
    extern __shared__ __nv_bfloat16 sm[];
    const uint32_t base = smem_u32(sm);

    const int tid = threadIdx.x;
    const int wid = tid >> 5, lane = tid & 31;
    const int wm = wid & 3, wn = wid >> 2;
    const int row0 = blockIdx.y * 128, col0 = blockIdx.x * 64;
    const int tileid = lane >> 3, rit = lane & 7;
    const int gid = lane >> 2, tig = lane & 3;
    const int bh = blockIdx.z;

    const __nv_bfloat16* Ab = A + (size_t)bh * aBS;
    const __nv_bfloat16* Bb = Bt + (size_t)bh * bBS + (size_t)col0 * K;

    float acc[2][4][4];
    #pragma unroll
    for (int mt = 0; mt < 2; mt++)
        #pragma unroll
        for (int j = 0; j < 4; j++)
            #pragma unroll
            for (int r = 0; r < 4; r++) acc[mt][j][r] = 0.f;

    const int nch = K >> 6;
    #pragma unroll
    for (int s = 0; s < 3; s++) {
        if (s < nch) {
            const int k0 = s << 6;
            const uint32_t aS = base + s * TG_STAGE;
            const uint32_t bS = aS + 16384;
            #pragma unroll
            for (int i = 0; i < 4; i++) {
                int lin = tid + i * 256;
                int r = lin >> 3, c8 = lin & 7;
                int rg = min(row0 + r, aClamp);
                cp_async16(aS + SWZ(r * 128 + c8 * 16), Ab + (size_t)rg * K + k0 + c8 * 8);
            }
            #pragma unroll
            for (int i = 0; i < 2; i++) {
                int lin = tid + i * 256;
                int r = lin >> 3, c8 = lin & 7;
                cp_async16(bS + SWZ(r * 128 + c8 * 16), Bb + (size_t)r * K + k0 + c8 * 8);
            }
        }
        cp_commit();
    }

    int stg = 0;
    for (int c = 0; c < nch; c++) {
        cp_wait2();
        __syncthreads();
        const uint32_t aB = base + stg * TG_STAGE;
        const uint32_t bB = aB + 16384;
        #pragma unroll
        for (int kk = 0; kk < 4; kk++) {
            uint32_t af[2][4];
            #pragma unroll
            for (int mt = 0; mt < 2; mt++) {
                int off = (wm * 32 + mt * 16 + (tileid & 1) * 8 + rit) * 128
                          + kk * 32 + (tileid >> 1) * 16;
                ldmatrix4(af[mt], aB + SWZ(off));
            }
            uint32_t bf[2][4];
            #pragma unroll
            for (int nt = 0; nt < 2; nt++) {
                int off = (wn * 32 + nt * 16 + (tileid & 1) * 8 + rit) * 128
                          + kk * 32 + (tileid >> 1) * 16;
                ldmatrix4(bf[nt], bB + SWZ(off));
            }
            #pragma unroll
            for (int mt = 0; mt < 2; mt++)
                #pragma unroll
                for (int j = 0; j < 4; j++) {
                    int nt = j >> 1, sel = j & 1;
                    mma16816(acc[mt][j], af[mt], bf[nt][sel], bf[nt][2 + sel]);
                }
        }
        __syncthreads();
        if (c + 3 < nch) {
            const int k0 = (c + 3) << 6;
            const uint32_t aS = base + stg * TG_STAGE;
            const uint32_t bS = aS + 16384;
            #pragma unroll
            for (int i = 0; i < 4; i++) {
                int lin = tid + i * 256;
                int r = lin >> 3, c8 = lin & 7;
                int rg = min(row0 + r, aClamp);
                cp_async16(aS + SWZ(r * 128 + c8 * 16), Ab + (size_t)rg * K + k0 + c8 * 8);
            }
            #pragma unroll
            for (int i = 0; i < 2; i++) {
                int lin = tid + i * 256;
                int r = lin >> 3, c8 = lin & 7;
                cp_async16(bS + SWZ(r * 128 + c8 * 16), Bb + (size_t)r * K + k0 + c8 * 8);
            }
        }
        cp_commit();
        stg = (stg + 1) == 3 ? 0 : stg + 1;
    }

    float* Cfb = Cf ? Cf + (size_t)bh * cBS : nullptr;
    __nv_bfloat16* Cbb = Cb ? Cb + (size_t)bh * cBS : nullptr;
    #pragma unroll
    for (int mt = 0; mt < 2; mt++) {
        #pragma unroll
        for (int j = 0; j < 4; j++) {
            #pragma unroll
            for (int half = 0; half < 2; half++) {
                int r = row0 + wm * 32 + mt * 16 + gid + half * 8;
                if (r >= mValid) continue;
                int cidx = col0 + wn * 32 + j * 8 + tig * 2;
                float v0 = acc[mt][j][half * 2 + 0];
                float v1 = acc[mt][j][half * 2 + 1];
                if (Cfb) *(float2*)(Cfb + (size_t)r * ldc + cidx) = make_float2(v0, v1);
                if (Cbb) *(__nv_bfloat162*)(Cbb + (size_t)r * ldc + cidx) = __floats2bfloat162_rn(v0, v1);
            }
        }
    }
}

// ---------------- prep kernels ----------------
__global__ void f2b_kernel(const float* __restrict__ a, __nv_bfloat16* __restrict__ b, size_t n) {
    size_t i = (size_t)blockIdx.x * blockDim.x + threadIdx.x;
    if (i < n) b[i] = __float2bfloat16(a[i]);
}

__global__ void wtrans_kernel(const float* __restrict__ W, __nv_bfloat16* __restrict__ Wt,
                              int K, int N) {
    __shared__ float t[32][33];
    int k0 = blockIdx.y * 32, n0 = blockIdx.x * 32;
    int tx = threadIdx.x, ty = threadIdx.y;
    #pragma unroll
    for (int i = 0; i < 32; i += 8)
        t[ty + i][tx] = W[(size_t)(k0 + ty + i) * N + n0 + tx];
    __syncthreads();
    #pragma unroll
    for (int i = 0; i < 32; i += 8)
        Wt[(size_t)(n0 + ty + i) * K + k0 + tx] = __float2bfloat16(t[tx][ty + i]);
}

__global__ void projb_kernel(const float* __restrict__ proj, __nv_bfloat16* __restrict__ pTb) {
    int i = blockIdx.x * 256 + threadIdx.x;
    if (i >= MP * 64) return;
    int m = i >> 6, d = i & 63;
    pTb[i] = __float2bfloat16((m < MF) ? proj[m * 64 + d] * NORM : 0.f);
}

// ---------------- layernorm ----------------
__global__ void ln_bf16_kernel(const float* __restrict__ x, const float* __restrict__ g,
                               const float* __restrict__ b, __nv_bfloat16* __restrict__ y)
{
    int row = blockIdx.x;
    int t = threadIdx.x;
    float v = x[(size_t)row * DIM + t];
    float mu = blockReduceSum256(v) * (1.0f / DIM);
    float d = v - mu;
    float var = blockReduceSum256(d * d) * (1.0f / DIM);
    y[(size_t)row * DIM + t] = __float2bfloat16(d * rsqrtf(var + LN_EPS) * g[t] + b[t]);
}

__global__ void ln_f32_kernel(const float* __restrict__ x, const float* __restrict__ g,
                              const float* __restrict__ b, float* __restrict__ y)
{
    int row = blockIdx.x;
    int t = threadIdx.x;
    float v = x[(size_t)row * DIM + t];
    float mu = blockReduceSum256(v) * (1.0f / DIM);
    float d = v - mu;
    float var = blockReduceSum256(d * d) * (1.0f / DIM);
    y[(size_t)row * DIM + t] = d * rsqrtf(var + LN_EPS) * g[t] + b[t];
}

// ---------------- FAVOR+ passes ----------------
__global__ void qexp_kernel(const __nv_bfloat16* __restrict__ qbuf, const float* __restrict__ dd,
                            __nv_bfloat16* __restrict__ qpB)
{
    int w = (blockIdx.x * 256 + threadIdx.x) >> 5;
    int lane = threadIdx.x & 31;
    if (w >= RH) return;
    const __nv_bfloat16* qr = qbuf + (size_t)w * 64;
    float a = __bfloat162float(qr[lane]), b2 = __bfloat162float(qr[lane + 32]);
    float s = a * a + b2 * b2;
    #pragma unroll
    for (int o = 16; o; o >>= 1) s += __shfl_xor_sync(0xFFFFFFFFu, s, o);
    float diag = 0.0625f * s;
    const float* row = dd + (size_t)w * MP;
    float vv[9], mx = -1e30f;
    #pragma unroll
    for (int i = 0; i < 9; i++) {
        int m = lane + 32 * i;
        vv[i] = (m < MF) ? row[m] : -1e30f;
        mx = fmaxf(mx, vv[i]);
    }
    #pragma unroll
    for (int o = 16; o; o >>= 1) mx = fmaxf(mx, __shfl_xor_sync(0xFFFFFFFFu, mx, o));

    int b = w / RPB;
    int rem = w - b * RPB;
    int n = rem >> 2, h = rem & 3;
    __nv_bfloat16* orow = qpB + ((size_t)(b * HEADS + h) * NN + n) * MP;
    #pragma unroll
    for (int i = 0; i < 9; i++) {
        int m = lane + 32 * i;
        if (m < MF) orow[m] = __float2bfloat16(RATIO * (__expf(vv[i] - diag - mx) + KEPS));
        else orow[m] = __float2bfloat16(0.f);
    }
    orow[lane + 288] = __float2bfloat16(0.f);
}

__global__ void kmax_init_kernel(int* __restrict__ kmax) {
    int i = blockIdx.x * blockDim.x + threadIdx.x;
    if (i < BH) kmax[i] = INT_MIN;
}

// kexp + transpose
__global__ void __launch_bounds__(256) kexpT_kernel(
    const __nv_bfloat16* __restrict__ kbuf, const float* __restrict__ dd,
    const int* __restrict__ kmax, __nv_bfloat16* __restrict__ kpT)
{
    __shared__ float s[32][325];
    __shared__ float diag[32];
    int bh = blockIdx.x, b = bh >> 2, h = bh & 3;
    int n0 = blockIdx.y * 32;
    int tid = threadIdx.x;
    int wid = tid >> 5, lane = tid & 31;

    #pragma unroll
    for (int ii = 0; ii < 4; ii++) {
        int n_l = wid * 4 + ii;
        int n_g = n0 + n_l;
        float sum = 0.f;
        if (n_g < NN) {
            const __nv_bfloat16* kr = kbuf + ((size_t)(b * NN + n_g)) * DIM + h * 64;
            float a = __bfloat162float(kr[lane]), b2 = __bfloat162float(kr[lane + 32]);
            sum = a * a + b2 * b2;
        }
        #pragma unroll
        for (int o = 16; o; o >>= 1) sum += __shfl_xor_sync(0xFFFFFFFFu, sum, o);
        if (lane == 0) diag[n_l] = 0.0625f * sum;
    }

    #pragma unroll
    for (int it = 0; it < 4; it++) {
        int n_l = (tid >> 5) + 8 * it;
        int n_g = n0 + n_l;
        const float* row = dd + ((size_t)((b * NN + min(n_g, NN - 1)) * HEADS) + h) * MP;
        bool ok = n_g < NN;
        #pragma unroll
        for (int j = 0; j < 10; j++) {
            int m = lane + 32 * j;
            s[n_l][m] = ok ? row[m] : 0.f;
        }
    }
    __syncthreads();

    float stab = o2f(kmax[bh]);
    int n_g = n0 + lane;
    bool nok = n_g < NN;
    float dg = diag[lane];
    __nv_bfloat16* base = kpT + (size_t)bh * MP * NP + n0 + lane;
    for (int m = wid; m < MP; m += 8) {
        float val = 0.f;
        if (m < MF && nok)
            val = RATIO * (__expf(s[lane][m] - dg - stab) + KEPS);
        base[(size_t)m * NP] = __float2bfloat16(val);
    }
}

// v transpose (bf16 in): vAugT[bh][d][n], d=64 row = ones
__global__ void __launch_bounds__(256) vtrans_kernel(
    const __nv_bfloat16* __restrict__ v, __nv_bfloat16* __restrict__ vT)
{
    __shared__ float t[32][65];
    int bh = blockIdx.x, b = bh >> 2, h = bh & 3;
    int tid = threadIdx.x;
    int lane = tid & 31;
    __nv_bfloat16* vb = vT + (size_t)bh * 128 * NP;

    for (int it = 0; it < 10; it++) {
        int n0 = it * 32;
        int d = tid & 63;
        #pragma unroll
        for (int sub = 0; sub < 8; sub++) {
            int n_l = (tid >> 6) + 4 * sub;
            int n_g = n0 + n_l;
            t[n_l][d] = (n_g < NN) ?
                __bfloat162float(v[((size_t)(b * NN + n_g)) * DIM + h * 64 + d]) : 0.f;
        }
        __syncthreads();
        int dcol = tid >> 5;
        #pragma unroll
        for (int j = 0; j < 8; j++) {
            int d2 = dcol + 8 * j;
            vb[(size_t)d2 * NP + n0 + lane] = __float2bfloat16(t[lane][d2]);
        }
        __syncthreads();
    }
    for (int idx = tid; idx < 64 * NP; idx += 256) {
        int d = 64 + idx / NP, n = idx % NP;
        float val = (d == 64 && n < NN) ? 1.f : 0.f;
        vb[(size_t)d * NP + n] = __float2bfloat16(val);
    }
}

__global__ void divout_kernel(const float* __restrict__ outA, __nv_bfloat16* __restrict__ ob)
{
    int bh = blockIdx.x, b = bh >> 2, h = bh & 3;
    const float* base = outA + (size_t)bh * NN * 128;
    for (int idx = threadIdx.x; idx < NN * 64; idx += 256) {
        int n = idx >> 6, d = idx & 63;
        float num = base[(size_t)n * 128 + d];
        float den = base[(size_t)n * 128 + 64];
        ob[((size_t)(b * NN + n)) * DIM + h * 64 + d] = __float2bfloat16(num / den);
    }
}

// ---------------- pooling & head ----------------
__global__ void pool_kernel(const float* __restrict__ h, float* __restrict__ pooled)
{
    int b = blockIdx.x, c = threadIdx.x;
    const float* p = h + (size_t)b * NN * DIM + c;
    float s0 = 0.f, s1 = 0.f, s2 = 0.f, s3 = 0.f;
    for (int n = 0; n < NN; n += 4) {
        s0 += p[(size_t)(n + 0) * DIM];
        s1 += p[(size_t)(n + 1) * DIM];
        s2 += p[(size_t)(n + 2) * DIM];
        s3 += p[(size_t)(n + 3) * DIM];
    }
    pooled[b * DIM + c] = ((s0 + s1) + (s2 + s3)) * (1.0f / NN);
}

__global__ void head1_kernel(const float* __restrict__ z, const float* __restrict__ w,
                             const float* __restrict__ bias, float* __restrict__ z1)
{
    __shared__ float zs[DIM];
    int b = blockIdx.x, j = threadIdx.x;
    for (int c = j; c < DIM; c += 128) zs[c] = z[b * DIM + c];
    __syncthreads();
    float s0 = 0.f, s1 = 0.f, s2 = 0.f, s3 = 0.f;
    #pragma unroll 1
    for (int c = 0; c < DIM; c += 4) {
        s0 = fmaf(zs[c + 0], w[(c + 0) * 128 + j], s0);
        s1 = fmaf(zs[c + 1], w[(c + 1) * 128 + j], s1);
        s2 = fmaf(zs[c + 2], w[(c + 2) * 128 + j], s2);
        s3 = fmaf(zs[c + 3], w[(c + 3) * 128 + j], s3);
    }
    z1[b * 128 + j] = fmaxf(((s0 + s1) + (s2 + s3)) + bias[j], 0.f);
}

__global__ void head2_kernel(const float* __restrict__ z1, const float* __restrict__ w,
                             const float* __restrict__ bias, float* __restrict__ out)
{
    __shared__ float sh[4];
    int b = blockIdx.x, j = threadIdx.x;
    float s = z1[b * 128 + j] * w[j];
    #pragma unroll
    for (int o = 16; o; o >>= 1) s += __shfl_xor_sync(0xFFFFFFFFu, s, o);
    if ((j & 31) == 0) sh[j >> 5] = s;
    __syncthreads();
    if (j == 0) {
        float t = sh[0] + sh[1] + sh[2] + sh[3] + bias[0];
        out[b] = 1.0f / (1.0f + __expf(-t));
    }
}

// ---------------- host ----------------
template <typename T> static T* symaddr(const void* sym) {
    void* p = nullptr;
    cudaGetSymbolAddress(&p, sym);
    return (T*)p;
}

extern "C" void kernel_launch(void* const* d_in, const int* in_sizes, int n_in,
                              void* d_out, int out_size)
{
    const float* x     = (const float*)d_in[0];
    const float* w_in  = (const float*)d_in[1];
    const float* b_in  = (const float*)d_in[2];
    const float* proj  = (const float*)d_in[3];
    const float* ln1_g = (const float*)d_in[4];
    const float* ln1_b = (const float*)d_in[5];
    const float* wq    = (const float*)d_in[6];
    const float* wk    = (const float*)d_in[7];
    const float* wv    = (const float*)d_in[8];
    const float* wo    = (const float*)d_in[9];
    const float* bo    = (const float*)d_in[10];
    const float* ln2_g = (const float*)d_in[11];
    const float* ln2_b = (const float*)d_in[12];
    const float* w1    = (const float*)d_in[13];
    const float* b1    = (const float*)d_in[14];
    const float* w2    = (const float*)d_in[15];
    const float* b2    = (const float*)d_in[16];
    const float* hln_g = (const float*)d_in[17];
    const float* hln_b = (const float*)d_in[18];
    const float* wh1   = (const float*)d_in[19];
    const float* bh1   = (const float*)d_in[20];
    const float* wh2   = (const float*)d_in[21];
    const float* bh2   = (const float*)d_in[22];
    float* out = (float*)d_out;

    float* h    = symaddr<float>(g_h);
    __nv_bfloat16* yb   = symaddr<__nv_bfloat16>(g_yb);
    __nv_bfloat16* qb   = symaddr<__nv_bfloat16>(g_qb);
    __nv_bfloat16* kb   = symaddr<__nv_bfloat16>(g_kb);
    __nv_bfloat16* vb   = symaddr<__nv_bfloat16>(g_vb);
    __nv_bfloat16* ob   = symaddr<__nv_bfloat16>(g_ob);
    __nv_bfloat16* ffhb = symaddr<__nv_bfloat16>(g_ffhb);
    __nv_bfloat16* xb   = symaddr<__nv_bfloat16>(g_xb);
    float* ddq  = symaddr<float>(g_ddq);
    float* ddk  = symaddr<float>(g_ddk);
    __nv_bfloat16* qpB  = symaddr<__nv_bfloat16>(g_qpB);
    __nv_bfloat16* kpT  = symaddr<__nv_bfloat16>(g_kpT);
    __nv_bfloat16* vT   = symaddr<__nv_bfloat16>(g_vT);
    __nv_bfloat16* ctxT = symaddr<__nv_bfloat16>(g_ctxT);
    float* outA = symaddr<float>(g_outA);
    int*   kmx  = symaddr<int>(g_kmax);
    float* pool = symaddr<float>(g_pool);
    float* z    = symaddr<float>(g_z);
    float* z1   = symaddr<float>(g_z1);
    __nv_bfloat16* pTb  = symaddr<__nv_bfloat16>(g_pTb);
    __nv_bfloat16* wInT = symaddr<__nv_bfloat16>(g_wInT);
    __nv_bfloat16* wqT  = symaddr<__nv_bfloat16>(g_wqT);
    __nv_bfloat16* wkT  = symaddr<__nv_bfloat16>(g_wkT);
    __nv_bfloat16* wvT  = symaddr<__nv_bfloat16>(g_wvT);
    __nv_bfloat16* woT  = symaddr<__nv_bfloat16>(g_woT);
    __nv_bfloat16* w1T  = symaddr<__nv_bfloat16>(g_w1T);
    __nv_bfloat16* w2T  = symaddr<__nv_bfloat16>(g_w2T);

    static bool attr_set = false;
    if (!attr_set) {
        cudaFuncSetAttribute(tgemm_kernel, cudaFuncAttributeMaxDynamicSharedMemorySize, TG_SMEM_BYTES);
        cudaFuncSetAttribute(btgemm_kernel, cudaFuncAttributeMaxDynamicSharedMemorySize, TG_SMEM_BYTES);
        attr_set = true;
    }

    dim3 blk256(256);
    dim3 t256(DIM / 64, ROWS_TOT / 128);
    dim3 t1024(FFH / 64, ROWS_TOT / 128);
    dim3 tdd(MP / 64, RH / 128);
    dim3 gCtx(MP / 64, 1, BH);
    dim3 gAtt(2, 3, BH);

    // ---- prep ----
    f2b_kernel<<<(int)((ROWS_TOT * (size_t)IN_DIM + 255) / 256), 256>>>(x, xb, (size_t)ROWS_TOT * IN_DIM);
    wtrans_kernel<<<dim3(DIM / 32, IN_DIM / 32), dim3(32, 8)>>>(w_in, wInT, IN_DIM, DIM);
    for (int l = 0; l < 2; l++) {
        wtrans_kernel<<<dim3(DIM / 32, DIM / 32), dim3(32, 8)>>>(wq + (size_t)l * DIM * DIM, wqT + (size_t)l * DIM * DIM, DIM, DIM);
        wtrans_kernel<<<dim3(DIM / 32, DIM / 32), dim3(32, 8)>>>(wk + (size_t)l * DIM * DIM, wkT + (size_t)l * DIM * DIM, DIM, DIM);
        wtrans_kernel<<<dim3(DIM / 32, DIM / 32), dim3(32, 8)>>>(wv + (size_t)l * DIM * DIM, wvT + (size_t)l * DIM * DIM, DIM, DIM);
        wtrans_kernel<<<dim3(DIM / 32, DIM / 32), dim3(32, 8)>>>(wo + (size_t)l * DIM * DIM, woT + (size_t)l * DIM * DIM, DIM, DIM);
        wtrans_kernel<<<dim3(FFH / 32, DIM / 32), dim3(32, 8)>>>(w1 + (size_t)l * DIM * FFH, w1T + (size_t)l * DIM * FFH, DIM, FFH);
        wtrans_kernel<<<dim3(DIM / 32, FFH / 32), dim3(32, 8)>>>(w2 + (size_t)l * FFH * DIM, w2T + (size_t)l * FFH * DIM, FFH, DIM);
    }

    tgemm_kernel<<<t256, blk256, TG_SMEM_BYTES>>>(xb, wInT, b_in, nullptr, h, nullptr,
                                                  ROWS_TOT, DIM, IN_DIM, 0, nullptr);

    for (int l = 0; l < 2; l++) {
        // --- attention ---
        ln_bf16_kernel<<<ROWS_TOT, 256>>>(h, ln1_g + l * DIM, ln1_b + l * DIM, yb);
        tgemm_kernel<<<t256, blk256, TG_SMEM_BYTES>>>(yb, wqT + (size_t)l * DIM * DIM, nullptr, nullptr, nullptr, qb, ROWS_TOT, DIM, DIM, 0, nullptr);
        tgemm_kernel<<<t256, blk256, TG_SMEM_BYTES>>>(yb, wkT + (size_t)l * DIM * DIM, nullptr, nullptr, nullptr, kb, ROWS_TOT, DIM, DIM, 0, nullptr);
        tgemm_kernel<<<t256, blk256, TG_SMEM_BYTES>>>(yb, wvT + (size_t)l * DIM * DIM, nullptr, nullptr, nullptr, vb, ROWS_TOT, DIM, DIM, 0, nullptr);

        projb_kernel<<<(MP * 64 + 255) / 256, 256>>>(proj + (size_t)l * MF * DH, pTb);
        kmax_init_kernel<<<1, 1024>>>(kmx);
        tgemm_kernel<<<tdd, blk256, TG_SMEM_BYTES>>>(qb, pTb, nullptr, nullptr, ddq, nullptr, RH, MP, 64, 0, nullptr);
        tgemm_kernel<<<tdd, blk256, TG_SMEM_BYTES>>>(kb, pTb, nullptr, nullptr, ddk, nullptr, RH, MP, 64, 0, kmx);

        qexp_kernel<<<RH / 8, 256>>>(qb, ddq, qpB);
        kexpT_kernel<<<dim3(BH, 10), 256>>>(kb, ddk, kmx, kpT);
        vtrans_kernel<<<BH, 256>>>(vb, vT);

        btgemm_kernel<<<gCtx, blk256, TG_SMEM_BYTES>>>(
            vT, (size_t)128 * NP, 127, kpT, (size_t)MP * NP,
            nullptr, ctxT, (size_t)128 * MP, MP, NP, 128);
        btgemm_kernel<<<gAtt, blk256, TG_SMEM_BYTES>>>(
            qpB, (size_t)NN * MP, NN - 1, ctxT, (size_t)128 * MP,
            outA, nullptr, (size_t)NN * 128, 128, MP, NN);

        divout_kernel<<<BH, 256>>>(outA, ob);

        tgemm_kernel<<<t256, blk256, TG_SMEM_BYTES>>>(ob, woT + (size_t)l * DIM * DIM, bo + l * DIM, h, h, nullptr, ROWS_TOT, DIM, DIM, 0, nullptr);

        // --- FFN ---
        ln_bf16_kernel<<<ROWS_TOT, 256>>>(h, ln2_g + l * DIM, ln2_b + l * DIM, yb);
        tgemm_kernel<<<t1024, blk256, TG_SMEM_BYTES>>>(yb, w1T + (size_t)l * DIM * FFH, b1 + l * FFH, nullptr, nullptr, ffhb, ROWS_TOT, FFH, DIM, 1, nullptr);
        tgemm_kernel<<<t256, blk256, TG_SMEM_BYTES>>>(ffhb, w2T + (size_t)l * FFH * DIM, b2 + l * DIM, h, h, nullptr, ROWS_TOT, DIM, FFH, 0, nullptr);
    }

    pool_kernel<<<BB, 256>>>(h, pool);
    ln_f32_kernel<<<BB, 256>>>(pool, hln_g, hln_b, z);
    head1_kernel<<<BB, 128>>>(z, wh1, bh1, z1);
    head2_kernel<<<BB, 128>>>(z1, wh2, bh2, out);
}